// round 1
// baseline (speedup 1.0000x reference)
#include <cuda_runtime.h>

// SoftAddressSpace: out[M,V] = softmax(selector[M,D] @ address_space[N,D]^T) @ param_bank[N,V]
// M = B*T = 16384, D = 128, N = 4096, V = 512. All fp32.
//
// R0 baseline: 3 passes.
//   1) gemm64<128, true>  : scores[M,N] = selector @ AS^T      (17.2 GFLOP)
//   2) softmax_rows       : row softmax over N=4096, in place  (0.5 GB traffic)
//   3) gemm64<4096,false> : out[M,V]   = W @ param_bank        (68.7 GFLOP)

#define M_TOT  16384
#define N_ADDR 4096
#define D_DIM  128
#define V_DIM  512

// 256 MiB scratch for the weight matrix (allowed: __device__ global, no allocs).
static __device__ float g_w[(size_t)M_TOT * (size_t)N_ADDR];

// ---------------------------------------------------------------------------
// Tiled SIMT GEMM: C[64x64 tile] = A[M,KTOT] @ B, fp32.
//   B_NK = true : B stored [N, KTOT] row-major (use B^T)   -> kernel 1
//   B_NK = false: B stored [KTOT, ldn] row-major           -> kernel 3
// 256 threads, 4x4 register micro-tile per thread, KC=32 k-chunks.
// Smem stored k-major with pad 68 (272B rows: 16B aligned, conflict-spread).
// ---------------------------------------------------------------------------
template <int KTOT, bool B_NK>
__global__ __launch_bounds__(256) void gemm64(
    const float* __restrict__ A,
    const float* __restrict__ B,
    float* __restrict__ C,
    int ldn,   // row stride of B when B_NK=false (elements)
    int ldc)   // row stride of C (elements)
{
    constexpr int KC = 32;
    __shared__ float As[KC][68];
    __shared__ float Bs[KC][68];

    const int tid = threadIdx.x;
    const int tx = tid & 15;        // 0..15  -> 4 cols each
    const int ty = tid >> 4;        // 0..15  -> 4 rows each
    const int m0 = blockIdx.y * 64;
    const int n0 = blockIdx.x * 64;

    float acc[4][4];
#pragma unroll
    for (int i = 0; i < 4; i++)
#pragma unroll
        for (int j = 0; j < 4; j++) acc[i][j] = 0.0f;

    for (int k0 = 0; k0 < KTOT; k0 += KC) {
        // --- load A tile (64 rows x KC k), transpose into k-major smem ---
#pragma unroll
        for (int it = 0; it < 8; ++it) {
            int i  = tid + it * 256;          // 0..2047
            int r  = i >> 5;                  // 0..63
            int kk = i & 31;                  // 0..31
            As[kk][r] = A[(size_t)(m0 + r) * KTOT + (k0 + kk)];
        }
        // --- load B tile ---
        if (B_NK) {
#pragma unroll
            for (int it = 0; it < 8; ++it) {
                int i  = tid + it * 256;
                int r  = i >> 5;              // n-local 0..63
                int kk = i & 31;
                Bs[kk][r] = B[(size_t)(n0 + r) * KTOT + (k0 + kk)];
            }
        } else {
#pragma unroll
            for (int it = 0; it < 8; ++it) {
                int i  = tid + it * 256;
                int c  = i & 63;              // n-local 0..63
                int kk = i >> 6;              // 0..31
                Bs[kk][c] = B[(size_t)(k0 + kk) * ldn + (n0 + c)];
            }
        }
        __syncthreads();

        // --- 4x4 micro-tile FMA over the k-chunk ---
#pragma unroll
        for (int kk = 0; kk < KC; kk++) {
            float4 a = *(const float4*)&As[kk][ty * 4];
            float4 b = *(const float4*)&Bs[kk][tx * 4];
            acc[0][0] += a.x * b.x; acc[0][1] += a.x * b.y; acc[0][2] += a.x * b.z; acc[0][3] += a.x * b.w;
            acc[1][0] += a.y * b.x; acc[1][1] += a.y * b.y; acc[1][2] += a.y * b.z; acc[1][3] += a.y * b.w;
            acc[2][0] += a.z * b.x; acc[2][1] += a.z * b.y; acc[2][2] += a.z * b.z; acc[2][3] += a.z * b.w;
            acc[3][0] += a.w * b.x; acc[3][1] += a.w * b.y; acc[3][2] += a.w * b.z; acc[3][3] += a.w * b.w;
        }
        __syncthreads();
    }

    // --- write C: float4 per row ---
#pragma unroll
    for (int i = 0; i < 4; i++) {
        float4 v = make_float4(acc[i][0], acc[i][1], acc[i][2], acc[i][3]);
        *(float4*)&C[(size_t)(m0 + ty * 4 + i) * ldc + (n0 + tx * 4)] = v;
    }
}

// ---------------------------------------------------------------------------
// Row softmax over N_ADDR=4096, one CTA (256 threads) per row.
// Row is held in 16 registers per thread: 1 global read + 1 global write.
// ---------------------------------------------------------------------------
__global__ __launch_bounds__(256) void softmax_rows(float* __restrict__ W)
{
    const int row = blockIdx.x;
    float* p = W + (size_t)row * N_ADDR;
    const int tid = threadIdx.x;

    float v[16];
    float mx = -1e30f;
#pragma unroll
    for (int i = 0; i < 16; i++) {
        v[i] = p[tid + i * 256];
        mx = fmaxf(mx, v[i]);
    }
    // warp-reduce max
#pragma unroll
    for (int o = 16; o; o >>= 1) mx = fmaxf(mx, __shfl_xor_sync(0xffffffffu, mx, o));
    __shared__ float smx[8];
    __shared__ float ssm[8];
    if ((tid & 31) == 0) smx[tid >> 5] = mx;
    __syncthreads();
    mx = smx[0];
#pragma unroll
    for (int i = 1; i < 8; i++) mx = fmaxf(mx, smx[i]);

    float s = 0.0f;
#pragma unroll
    for (int i = 0; i < 16; i++) {
        v[i] = __expf(v[i] - mx);
        s += v[i];
    }
#pragma unroll
    for (int o = 16; o; o >>= 1) s += __shfl_xor_sync(0xffffffffu, s, o);
    if ((tid & 31) == 0) ssm[tid >> 5] = s;
    __syncthreads();
    s = 0.0f;
#pragma unroll
    for (int i = 0; i < 8; i++) s += ssm[i];

    const float inv = 1.0f / s;
#pragma unroll
    for (int i = 0; i < 16; i++) p[tid + i * 256] = v[i] * inv;
}

// ---------------------------------------------------------------------------
extern "C" void kernel_launch(void* const* d_in, const int* in_sizes, int n_in,
                              void* d_out, int out_size)
{
    const float* selector      = (const float*)d_in[0];  // [16384, 128]
    const float* param_bank    = (const float*)d_in[1];  // [4096, 512]
    const float* address_space = (const float*)d_in[2];  // [4096, 128]
    float* out = (float*)d_out;                          // [16384, 512]

    float* w;
    cudaGetSymbolAddress((void**)&w, g_w);

    // Pass 1: scores = selector @ AS^T  -> g_w
    {
        dim3 grid(N_ADDR / 64, M_TOT / 64);
        gemm64<D_DIM, true><<<grid, 256>>>(selector, address_space, w,
                                           /*ldn=*/0, /*ldc=*/N_ADDR);
    }
    // Pass 2: row softmax in place
    softmax_rows<<<M_TOT, 256>>>(w);

    // Pass 3: out = W @ param_bank
    {
        dim3 grid(V_DIM / 64, M_TOT / 64);
        gemm64<N_ADDR, false><<<grid, 256>>>(w, param_bank, out,
                                             /*ldn=*/V_DIM, /*ldc=*/V_DIM);
    }
}

// round 3
// speedup vs baseline: 2.8595x; 2.8595x over previous
#include <cuda_runtime.h>
#include <cstdint>

// SoftAddressSpace: out[M,V] = softmax(selector[M,D] @ AS[N,D]^T) @ PB[N,V]
// M=16384, D=128, N=4096, V=512, fp32.
// R2: tcgen05 unavailable (harness PTX target is sm_103 without the 'a'
// feature), so both GEMMs use legacy mma.sync.m16n8k8 tf32 (HMMA fallback).
//   GEMM1: 3xTF32 hi/lo split -> fp32-grade scores for softmax.
//   GEMM2: plain rna-rounded tf32 (~5e-4 output rel err).

#define M_TOT  16384
#define N_ADDR 4096
#define D_DIM  128
#define V_DIM  512

static __device__ float g_w[(size_t)M_TOT * N_ADDR];     // 256 MiB scores/weights
static __device__ float g_pbt[(size_t)V_DIM * N_ADDR];   // 8 MiB param_bank^T

__device__ __forceinline__ float tf32_rna(float x) {
    uint32_t r;
    asm("cvt.rna.tf32.f32 %0, %1;" : "=r"(r) : "f"(x));
    return __uint_as_float(r);
}

__device__ __forceinline__ void mma8(float* d, const uint32_t* a, const uint32_t* b) {
    asm volatile(
        "mma.sync.aligned.m16n8k8.row.col.f32.tf32.tf32.f32 "
        "{%0,%1,%2,%3}, {%4,%5,%6,%7}, {%8,%9}, {%0,%1,%2,%3};"
        : "+f"(d[0]), "+f"(d[1]), "+f"(d[2]), "+f"(d[3])
        : "r"(a[0]), "r"(a[1]), "r"(a[2]), "r"(a[3]), "r"(b[0]), "r"(b[1]));
}

// ---------------------------------------------------------------------------
// C[M,N] = A[M,KTOT] @ B[N,KTOT]^T, all row-major, fp32 in/out.
// CTA tile 128x128, 8 warps (2m x 4n) of 64x32, KC=32, 2-stage smem.
// Smem rows padded to 36 floats -> fragment LDS is bank-conflict-free.
// SPLIT: 3xTF32 (hi/lo operand split) for fp32-grade accuracy.
// ---------------------------------------------------------------------------
template <int KTOT, bool SPLIT>
__global__ __launch_bounds__(256) void mma_gemm(const float* __restrict__ A,
                                                const float* __restrict__ B,
                                                float* __restrict__ C, int ldc)
{
    constexpr int KC = 32;
    constexpr int CHUNKS = KTOT / KC;
    constexpr int LDSM = 36;            // floats per smem row (pad)
    constexpr int TILE_F = 128 * LDSM;  // 4608 floats per 128x32 tile
    constexpr int NARR = SPLIT ? 2 : 1;
    constexpr int STAGE_F = TILE_F * 2 * NARR;

    extern __shared__ float sm[];

    const int tid  = threadIdx.x;
    const int lane = tid & 31;
    const int wid  = tid >> 5;
    const int wm   = wid & 1;          // 0..1 -> 64-row slab
    const int wn   = wid >> 1;         // 0..3 -> 32-col slab
    const int m0   = blockIdx.y * 128;
    const int n0   = blockIdx.x * 128;
    const int lg   = lane >> 2;        // 0..7
    const int lt   = lane & 3;         // 0..3

    float acc[4][4][4];
#pragma unroll
    for (int i = 0; i < 4; i++)
#pragma unroll
        for (int j = 0; j < 4; j++)
#pragma unroll
            for (int k = 0; k < 4; k++) acc[i][j][k] = 0.0f;

    float4 rA[4], rB[4];

    auto ldg = [&](int k0) {
#pragma unroll
        for (int it = 0; it < 4; it++) {
            int idx = tid + it * 256;
            int r = idx >> 3, c4 = idx & 7;
            rA[it] = *(const float4*)(A + (size_t)(m0 + r) * KTOT + k0 + c4 * 4);
            rB[it] = *(const float4*)(B + (size_t)(n0 + r) * KTOT + k0 + c4 * 4);
        }
    };

    auto sts = [&](int s) {
        float* ah = sm + s * STAGE_F;
        float* bh = ah + TILE_F * NARR;
#pragma unroll
        for (int it = 0; it < 4; it++) {
            int idx = tid + it * 256;
            int r = idx >> 3, c4 = idx & 7;
            int off = r * LDSM + c4 * 4;
            float4 va = rA[it], vb = rB[it];
            if (SPLIT) {
                float4 h, l;
                h.x = tf32_rna(va.x); h.y = tf32_rna(va.y); h.z = tf32_rna(va.z); h.w = tf32_rna(va.w);
                l.x = tf32_rna(va.x - h.x); l.y = tf32_rna(va.y - h.y);
                l.z = tf32_rna(va.z - h.z); l.w = tf32_rna(va.w - h.w);
                *(float4*)(ah + off) = h;
                *(float4*)(ah + TILE_F + off) = l;
                h.x = tf32_rna(vb.x); h.y = tf32_rna(vb.y); h.z = tf32_rna(vb.z); h.w = tf32_rna(vb.w);
                l.x = tf32_rna(vb.x - h.x); l.y = tf32_rna(vb.y - h.y);
                l.z = tf32_rna(vb.z - h.z); l.w = tf32_rna(vb.w - h.w);
                *(float4*)(bh + off) = h;
                *(float4*)(bh + TILE_F + off) = l;
            } else {
                va.x = tf32_rna(va.x); va.y = tf32_rna(va.y); va.z = tf32_rna(va.z); va.w = tf32_rna(va.w);
                vb.x = tf32_rna(vb.x); vb.y = tf32_rna(vb.y); vb.z = tf32_rna(vb.z); vb.w = tf32_rna(vb.w);
                *(float4*)(ah + off) = va;
                *(float4*)(bh + off) = vb;
            }
        }
    };

    auto compute = [&](int s) {
        const float* ah = sm + s * STAGE_F;
        const float* bh = ah + TILE_F * NARR;
        const float* al = ah + TILE_F;   // valid iff SPLIT
        const float* bl = bh + TILE_F;
#pragma unroll
        for (int ks = 0; ks < 4; ks++) {
            const int c = ks * 8 + lt;
            uint32_t afh[4][4], bfh[4][2];
            uint32_t afl[4][4], bfl[4][2];
#pragma unroll
            for (int mf = 0; mf < 4; mf++) {
                const int rb = wm * 64 + mf * 16 + lg;
                afh[mf][0] = __float_as_uint(ah[rb * LDSM + c]);
                afh[mf][1] = __float_as_uint(ah[(rb + 8) * LDSM + c]);
                afh[mf][2] = __float_as_uint(ah[rb * LDSM + c + 4]);
                afh[mf][3] = __float_as_uint(ah[(rb + 8) * LDSM + c + 4]);
                if (SPLIT) {
                    afl[mf][0] = __float_as_uint(al[rb * LDSM + c]);
                    afl[mf][1] = __float_as_uint(al[(rb + 8) * LDSM + c]);
                    afl[mf][2] = __float_as_uint(al[rb * LDSM + c + 4]);
                    afl[mf][3] = __float_as_uint(al[(rb + 8) * LDSM + c + 4]);
                }
            }
#pragma unroll
            for (int nf = 0; nf < 4; nf++) {
                const int nb = wn * 32 + nf * 8 + lg;
                bfh[nf][0] = __float_as_uint(bh[nb * LDSM + c]);
                bfh[nf][1] = __float_as_uint(bh[nb * LDSM + c + 4]);
                if (SPLIT) {
                    bfl[nf][0] = __float_as_uint(bl[nb * LDSM + c]);
                    bfl[nf][1] = __float_as_uint(bl[nb * LDSM + c + 4]);
                }
            }
#pragma unroll
            for (int mf = 0; mf < 4; mf++)
#pragma unroll
                for (int nf = 0; nf < 4; nf++) {
                    mma8(acc[mf][nf], afh[mf], bfh[nf]);
                    if (SPLIT) {
                        mma8(acc[mf][nf], afh[mf], bfl[nf]);
                        mma8(acc[mf][nf], afl[mf], bfh[nf]);
                    }
                }
        }
    };

    ldg(0);
    sts(0);
    for (int i = 0; i < CHUNKS; i++) {
        __syncthreads();
        if (i + 1 < CHUNKS) ldg((i + 1) * KC);
        compute(i & 1);
        if (i + 1 < CHUNKS) sts((i + 1) & 1);
    }

    // Epilogue: c0/c1 -> (row, 2c..2c+1); c2/c3 -> (row+8, same cols)
#pragma unroll
    for (int mf = 0; mf < 4; mf++) {
        const int row = m0 + wm * 64 + mf * 16 + lg;
#pragma unroll
        for (int nf = 0; nf < 4; nf++) {
            const int col = n0 + wn * 32 + nf * 8 + lt * 2;
            *(float2*)(C + (size_t)row * ldc + col) =
                make_float2(acc[mf][nf][0], acc[mf][nf][1]);
            *(float2*)(C + (size_t)(row + 8) * ldc + col) =
                make_float2(acc[mf][nf][2], acc[mf][nf][3]);
        }
    }
}

// ---------------------------------------------------------------------------
// param_bank [N,V] -> PBT [V,N]
// ---------------------------------------------------------------------------
__global__ __launch_bounds__(256) void transpose_pb(const float* __restrict__ PB,
                                                    float* __restrict__ PBT)
{
    __shared__ float t[32][33];
    const int bx = blockIdx.x * 32;  // V
    const int by = blockIdx.y * 32;  // N
    const int x = threadIdx.x & 31;
    const int y = threadIdx.x >> 5;  // 0..7
#pragma unroll
    for (int j = 0; j < 32; j += 8)
        t[y + j][x] = PB[(size_t)(by + y + j) * V_DIM + bx + x];
    __syncthreads();
#pragma unroll
    for (int j = 0; j < 32; j += 8)
        PBT[(size_t)(bx + y + j) * N_ADDR + by + x] = t[x][y + j];
}

// ---------------------------------------------------------------------------
// Row softmax over N_ADDR=4096, one CTA (256 threads) per row, in place.
// ---------------------------------------------------------------------------
__global__ __launch_bounds__(256) void softmax_rows(float* __restrict__ W)
{
    const int row = blockIdx.x;
    float* p = W + (size_t)row * N_ADDR;
    const int tid = threadIdx.x;

    float v[16];
    float mx = -1e30f;
#pragma unroll
    for (int i = 0; i < 16; i++) {
        v[i] = p[tid + i * 256];
        mx = fmaxf(mx, v[i]);
    }
#pragma unroll
    for (int o = 16; o; o >>= 1) mx = fmaxf(mx, __shfl_xor_sync(0xffffffffu, mx, o));
    __shared__ float smx[8];
    __shared__ float ssm[8];
    if ((tid & 31) == 0) smx[tid >> 5] = mx;
    __syncthreads();
    mx = smx[0];
#pragma unroll
    for (int i = 1; i < 8; i++) mx = fmaxf(mx, smx[i]);

    float s = 0.0f;
#pragma unroll
    for (int i = 0; i < 16; i++) {
        v[i] = __expf(v[i] - mx);
        s += v[i];
    }
#pragma unroll
    for (int o = 16; o; o >>= 1) s += __shfl_xor_sync(0xffffffffu, s, o);
    if ((tid & 31) == 0) ssm[tid >> 5] = s;
    __syncthreads();
    s = 0.0f;
#pragma unroll
    for (int i = 0; i < 8; i++) s += ssm[i];

    const float inv = 1.0f / s;
#pragma unroll
    for (int i = 0; i < 16; i++) p[tid + i * 256] = v[i] * inv;
}

// ---------------------------------------------------------------------------
extern "C" void kernel_launch(void* const* d_in, const int* in_sizes, int n_in,
                              void* d_out, int out_size)
{
    const float* selector      = (const float*)d_in[0];  // [16384, 128]
    const float* param_bank    = (const float*)d_in[1];  // [4096, 512]
    const float* address_space = (const float*)d_in[2];  // [4096, 128]
    float* out = (float*)d_out;                          // [16384, 512]

    float* w;   cudaGetSymbolAddress((void**)&w, g_w);
    float* pbt; cudaGetSymbolAddress((void**)&pbt, g_pbt);

    constexpr uint32_t SMEM1 = 2u * (128 * 36) * 2 * 2 * 4;  // split: 147456 B
    constexpr uint32_t SMEM2 = 2u * (128 * 36) * 2 * 1 * 4;  // plain:  73728 B
    cudaFuncSetAttribute(mma_gemm<D_DIM, true>,
                         cudaFuncAttributeMaxDynamicSharedMemorySize, SMEM1);
    cudaFuncSetAttribute(mma_gemm<N_ADDR, false>,
                         cudaFuncAttributeMaxDynamicSharedMemorySize, SMEM2);

    // Pass 0: PB^T
    transpose_pb<<<dim3(V_DIM / 32, N_ADDR / 32), 256>>>(param_bank, pbt);

    // Pass 1: scores = selector @ AS^T  (3xTF32 split)
    mma_gemm<D_DIM, true><<<dim3(N_ADDR / 128, M_TOT / 128), 256, SMEM1>>>(
        selector, address_space, w, N_ADDR);

    // Pass 2: row softmax in place
    softmax_rows<<<M_TOT, 256>>>(w);

    // Pass 3: out = W @ PBT^T
    mma_gemm<N_ADDR, false><<<dim3(V_DIM / 128, M_TOT / 128), 256, SMEM2>>>(
        w, pbt, out, V_DIM);
}

// round 4
// speedup vs baseline: 5.6787x; 1.9859x over previous
#include <cuda_runtime.h>
#include <cuda_fp16.h>
#include <cstdint>

// SoftAddressSpace: out[M,V] = softmax(selector[M,D] @ AS[N,D]^T) @ PB[N,V]
// M=16384, D=128, N=4096, V=512, fp32 in/out.
// R3: fp16 HMMA (m16n8k16) + ldmatrix + cp.async.
//   GEMM1 (scores): hi/lo fp16 split, 3 terms -> fp32-grade scores.
//   softmax: f32 scores -> fp16 weights.
//   GEMM2: plain fp16 (weights x param_bank^T), fp32 accum.

#define M_TOT  16384
#define N_ADDR 4096
#define D_DIM  128
#define V_DIM  512

static __device__ float  g_w  [(size_t)M_TOT * N_ADDR];   // f32 scores (256 MiB)
static __device__ __half g_wh [(size_t)M_TOT * N_ADDR];   // fp16 weights (128 MiB)
static __device__ __half g_pbt[(size_t)V_DIM * N_ADDR];   // fp16 PB^T (4 MiB)

__device__ __forceinline__ uint32_t smem_u32(const void* p) {
    uint32_t a;
    asm("{ .reg .u64 t; cvta.to.shared.u64 t, %1; cvt.u32.u64 %0, t; }" : "=r"(a) : "l"(p));
    return a;
}

#define LDSM_X4(r0, r1, r2, r3, addr) \
    asm volatile("ldmatrix.sync.aligned.m8n8.x4.shared.b16 {%0,%1,%2,%3}, [%4];" \
                 : "=r"(r0), "=r"(r1), "=r"(r2), "=r"(r3) : "r"(addr))

__device__ __forceinline__ void mma16816(float* d, const uint32_t* a, const uint32_t* b) {
    asm volatile(
        "mma.sync.aligned.m16n8k16.row.col.f32.f16.f16.f32 "
        "{%0,%1,%2,%3}, {%4,%5,%6,%7}, {%8,%9}, {%0,%1,%2,%3};"
        : "+f"(d[0]), "+f"(d[1]), "+f"(d[2]), "+f"(d[3])
        : "r"(a[0]), "r"(a[1]), "r"(a[2]), "r"(a[3]), "r"(b[0]), "r"(b[1]));
}

__device__ __forceinline__ void cp16(uint32_t dst, const void* src) {
    asm volatile("cp.async.cg.shared.global [%0], [%1], 16;" :: "r"(dst), "l"(src));
}
#define CP_COMMIT() asm volatile("cp.async.commit_group;" ::: "memory")
#define CP_WAIT1()  asm volatile("cp.async.wait_group 1;" ::: "memory")

// ---------------------------------------------------------------------------
// GEMM1: scores[M,N] = selector[M,128] @ AS[N,128]^T, hi/lo fp16 split.
// CTA tile 128x64, 8 warps (2m x 4n), warp tile 64x16.
// All four fp16 tiles (Ah, Al, Bh, Bl) resident in smem; 3 terms x 8 k-steps.
// Smem rows: 128 halves = 256B, swizzle: chunk ^= (row & 7).
// ---------------------------------------------------------------------------
__global__ __launch_bounds__(256, 2) void score_gemm(
    const float* __restrict__ S, const float* __restrict__ AS,
    float* __restrict__ W)
{
    extern __shared__ char sm[];
    // Ah @0 (32KB), Al @32768, Bh @65536 (16KB), Bl @81920; total 96KB
    const uint32_t sb = smem_u32(sm);
    const int tid = threadIdx.x, lane = tid & 31, wid = tid >> 5;
    const int wm = wid & 1, wn = wid >> 1;
    const int m0 = blockIdx.y * 128, n0 = blockIdx.x * 64;

    auto cvt_store = [&](const float* src, uint32_t dh, uint32_t dl) {
        float4 v0 = *(const float4*)src, v1 = *(const float4*)(src + 4);
        float f[8] = {v0.x, v0.y, v0.z, v0.w, v1.x, v1.y, v1.z, v1.w};
        uint32_t hh[4], ll[4];
#pragma unroll
        for (int j = 0; j < 4; j++) {
            __half h0 = __float2half_rn(f[2 * j]);
            __half h1 = __float2half_rn(f[2 * j + 1]);
            __half l0 = __float2half_rn(f[2 * j]     - __half2float(h0));
            __half l1 = __float2half_rn(f[2 * j + 1] - __half2float(h1));
            __half2 hp = __halves2half2(h0, h1);
            __half2 lp = __halves2half2(l0, l1);
            hh[j] = *(uint32_t*)&hp;
            ll[j] = *(uint32_t*)&lp;
        }
        *(uint4*)(sm + dh) = make_uint4(hh[0], hh[1], hh[2], hh[3]);
        *(uint4*)(sm + dl) = make_uint4(ll[0], ll[1], ll[2], ll[3]);
    };

    // Load + convert A (128 rows x 128 f32)
#pragma unroll
    for (int s = 0; s < 8; s++) {
        int idx = tid + s * 256;            // 0..2047
        int r = idx >> 4, b = idx & 15;
        uint32_t off = (uint32_t)(r * 256 + b * 16);
        uint32_t sw = off ^ (((off >> 8) & 7) << 4);
        cvt_store(S + (size_t)(m0 + r) * D_DIM + b * 8, sw, 32768 + sw);
    }
    // Load + convert B (64 rows x 128 f32)
#pragma unroll
    for (int s = 0; s < 4; s++) {
        int idx = tid + s * 256;            // 0..1023
        int r = idx >> 4, b = idx & 15;
        uint32_t off = (uint32_t)(r * 256 + b * 16);
        uint32_t sw = off ^ (((off >> 8) & 7) << 4);
        cvt_store(AS + (size_t)(n0 + r) * D_DIM + b * 8, 65536 + sw, 81920 + sw);
    }
    __syncthreads();

    float acc[4][2][4];
#pragma unroll
    for (int i = 0; i < 4; i++)
#pragma unroll
        for (int j = 0; j < 2; j++)
#pragma unroll
            for (int k = 0; k < 4; k++) acc[i][j][k] = 0.0f;

    const int sub = lane >> 3, rr = lane & 7;

#pragma unroll
    for (int t = 0; t < 3; t++) {
        const uint32_t ab = sb + (t == 2 ? 32768u : 0u);
        const uint32_t bb = sb + (t == 1 ? 81920u : 65536u);
#pragma unroll
        for (int ks = 0; ks < 8; ks++) {
            uint32_t a[4][4];
#pragma unroll
            for (int mf = 0; mf < 4; mf++) {
                int row = wm * 64 + mf * 16 + ((sub & 1) << 3) + rr;
                uint32_t off = (uint32_t)(row * 256 + ks * 32 + ((sub >> 1) << 4));
                uint32_t sw = off ^ (((off >> 8) & 7) << 4);
                LDSM_X4(a[mf][0], a[mf][1], a[mf][2], a[mf][3], ab + sw);
            }
            uint32_t bf[4];
            {
                int nrow = wn * 16 + ((sub >> 1) << 3) + rr;
                uint32_t off = (uint32_t)(nrow * 256 + ks * 32 + ((sub & 1) << 4));
                uint32_t sw = off ^ (((off >> 8) & 7) << 4);
                LDSM_X4(bf[0], bf[1], bf[2], bf[3], bb + sw);
            }
#pragma unroll
            for (int mf = 0; mf < 4; mf++)
#pragma unroll
                for (int nf = 0; nf < 2; nf++)
                    mma16816(acc[mf][nf], a[mf], &bf[nf * 2]);
        }
    }

    const int lg = lane >> 2, lt = lane & 3;
#pragma unroll
    for (int mf = 0; mf < 4; mf++) {
        const int row = m0 + wm * 64 + mf * 16 + lg;
#pragma unroll
        for (int nf = 0; nf < 2; nf++) {
            const int col = n0 + wn * 16 + nf * 8 + lt * 2;
            *(float2*)(W + (size_t)row * N_ADDR + col) =
                make_float2(acc[mf][nf][0], acc[mf][nf][1]);
            *(float2*)(W + (size_t)(row + 8) * N_ADDR + col) =
                make_float2(acc[mf][nf][2], acc[mf][nf][3]);
        }
    }
}

// ---------------------------------------------------------------------------
// GEMM2: out[M,V] = Wh[M,4096] @ PBT[V,4096]^T, fp16 x fp16 -> fp32.
// CTA tile 128x128, 8 warps (2m x 4n), warp tile 64x32.
// KC=64 halves (128B rows), cp.async 3-stage pipeline.
// ---------------------------------------------------------------------------
__global__ __launch_bounds__(256, 2) void out_gemm(
    const __half* __restrict__ Wh, const __half* __restrict__ PBT,
    float* __restrict__ C)
{
    extern __shared__ char sm[];
    // stage st: A @ st*32768 (16KB), B @ st*32768 + 16384; 3 stages = 96KB
    const uint32_t sb = smem_u32(sm);
    const int tid = threadIdx.x, lane = tid & 31, wid = tid >> 5;
    const int wm = wid & 1, wn = wid >> 1;
    const int m0 = blockIdx.y * 128, n0 = blockIdx.x * 128;
    constexpr int CHUNKS = N_ADDR / 64;

    auto issue = [&](int st, int ci) {
        const uint32_t base = (uint32_t)st * 32768u;
        const int k0 = ci * 64;
#pragma unroll
        for (int s = 0; s < 4; s++) {
            int idx = tid + s * 256;        // 0..1023
            int r = idx >> 3, b = idx & 7;
            uint32_t off = (uint32_t)(r * 128 + b * 16);
            uint32_t sw = off ^ ((off >> 3) & 0x70);
            cp16(sb + base + sw,          Wh  + (size_t)(m0 + r) * N_ADDR + k0 + b * 8);
            cp16(sb + base + 16384 + sw,  PBT + (size_t)(n0 + r) * N_ADDR + k0 + b * 8);
        }
        CP_COMMIT();
    };

    float acc[4][4][4];
#pragma unroll
    for (int i = 0; i < 4; i++)
#pragma unroll
        for (int j = 0; j < 4; j++)
#pragma unroll
            for (int k = 0; k < 4; k++) acc[i][j][k] = 0.0f;

    issue(0, 0);
    issue(1, 1);

    const int sub = lane >> 3, rr = lane & 7;

    for (int ci = 0; ci < CHUNKS; ci++) {
        const int st = ci % 3;
        CP_WAIT1();
        __syncthreads();
        if (ci + 2 < CHUNKS) issue((ci + 2) % 3, ci + 2);

        const uint32_t ab = sb + (uint32_t)st * 32768u;
        const uint32_t bb = ab + 16384u;
#pragma unroll
        for (int ks = 0; ks < 4; ks++) {
            uint32_t a[4][4];
#pragma unroll
            for (int mf = 0; mf < 4; mf++) {
                int row = wm * 64 + mf * 16 + ((sub & 1) << 3) + rr;
                uint32_t off = (uint32_t)(row * 128 + ks * 32 + ((sub >> 1) << 4));
                uint32_t sw = off ^ ((off >> 3) & 0x70);
                LDSM_X4(a[mf][0], a[mf][1], a[mf][2], a[mf][3], ab + sw);
            }
            uint32_t bf[8];
#pragma unroll
            for (int p = 0; p < 2; p++) {
                int nrow = wn * 32 + (p * 2 + (sub >> 1)) * 8 + rr;
                uint32_t off = (uint32_t)(nrow * 128 + ks * 32 + ((sub & 1) << 4));
                uint32_t sw = off ^ ((off >> 3) & 0x70);
                LDSM_X4(bf[p * 4], bf[p * 4 + 1], bf[p * 4 + 2], bf[p * 4 + 3], bb + sw);
            }
#pragma unroll
            for (int mf = 0; mf < 4; mf++)
#pragma unroll
                for (int nf = 0; nf < 4; nf++)
                    mma16816(acc[mf][nf], a[mf], &bf[nf * 2]);
        }
    }

    const int lg = lane >> 2, lt = lane & 3;
#pragma unroll
    for (int mf = 0; mf < 4; mf++) {
        const int row = m0 + wm * 64 + mf * 16 + lg;
#pragma unroll
        for (int nf = 0; nf < 4; nf++) {
            const int col = n0 + wn * 32 + nf * 8 + lt * 2;
            *(float2*)(C + (size_t)row * V_DIM + col) =
                make_float2(acc[mf][nf][0], acc[mf][nf][1]);
            *(float2*)(C + (size_t)(row + 8) * V_DIM + col) =
                make_float2(acc[mf][nf][2], acc[mf][nf][3]);
        }
    }
}

// ---------------------------------------------------------------------------
// Row softmax: f32 scores -> fp16 weights. One CTA (256 thr) per row.
// ---------------------------------------------------------------------------
__global__ __launch_bounds__(256) void softmax_rows(
    const float* __restrict__ W, __half* __restrict__ Wh)
{
    const int row = blockIdx.x;
    const float2* p = (const float2*)(W + (size_t)row * N_ADDR);
    __half2* q = (__half2*)(Wh + (size_t)row * N_ADDR);
    const int tid = threadIdx.x;

    float2 v[8];
    float mx = -1e30f;
#pragma unroll
    for (int i = 0; i < 8; i++) {
        v[i] = p[tid + i * 256];
        mx = fmaxf(mx, fmaxf(v[i].x, v[i].y));
    }
#pragma unroll
    for (int o = 16; o; o >>= 1) mx = fmaxf(mx, __shfl_xor_sync(0xffffffffu, mx, o));
    __shared__ float smx[8], ssm[8];
    if ((tid & 31) == 0) smx[tid >> 5] = mx;
    __syncthreads();
    mx = smx[0];
#pragma unroll
    for (int i = 1; i < 8; i++) mx = fmaxf(mx, smx[i]);

    float s = 0.0f;
#pragma unroll
    for (int i = 0; i < 8; i++) {
        v[i].x = __expf(v[i].x - mx);
        v[i].y = __expf(v[i].y - mx);
        s += v[i].x + v[i].y;
    }
#pragma unroll
    for (int o = 16; o; o >>= 1) s += __shfl_xor_sync(0xffffffffu, s, o);
    if ((tid & 31) == 0) ssm[tid >> 5] = s;
    __syncthreads();
    s = 0.0f;
#pragma unroll
    for (int i = 0; i < 8; i++) s += ssm[i];

    const float inv = 1.0f / s;
#pragma unroll
    for (int i = 0; i < 8; i++)
        q[tid + i * 256] = __floats2half2_rn(v[i].x * inv, v[i].y * inv);
}

// ---------------------------------------------------------------------------
// param_bank [N,V] f32 -> PBT [V,N] fp16
// ---------------------------------------------------------------------------
__global__ __launch_bounds__(256) void transpose_pb(
    const float* __restrict__ PB, __half* __restrict__ PBT)
{
    __shared__ float t[32][33];
    const int bx = blockIdx.x * 32;  // V
    const int by = blockIdx.y * 32;  // N
    const int x = threadIdx.x & 31;
    const int y = threadIdx.x >> 5;  // 0..7
#pragma unroll
    for (int j = 0; j < 32; j += 8)
        t[y + j][x] = PB[(size_t)(by + y + j) * V_DIM + bx + x];
    __syncthreads();
#pragma unroll
    for (int j = 0; j < 32; j += 8)
        PBT[(size_t)(bx + y + j) * N_ADDR + by + x] = __float2half_rn(t[x][y + j]);
}

// ---------------------------------------------------------------------------
extern "C" void kernel_launch(void* const* d_in, const int* in_sizes, int n_in,
                              void* d_out, int out_size)
{
    const float* selector      = (const float*)d_in[0];  // [16384, 128]
    const float* param_bank    = (const float*)d_in[1];  // [4096, 512]
    const float* address_space = (const float*)d_in[2];  // [4096, 128]
    float* out = (float*)d_out;                          // [16384, 512]

    float*  w;   cudaGetSymbolAddress((void**)&w,   g_w);
    __half* wh;  cudaGetSymbolAddress((void**)&wh,  g_wh);
    __half* pbt; cudaGetSymbolAddress((void**)&pbt, g_pbt);

    constexpr uint32_t SMEM1 = 98304;   // 96KB (Ah+Al+Bh+Bl)
    constexpr uint32_t SMEM2 = 98304;   // 96KB (3 x 32KB stages)
    cudaFuncSetAttribute(score_gemm, cudaFuncAttributeMaxDynamicSharedMemorySize, SMEM1);
    cudaFuncSetAttribute(out_gemm,   cudaFuncAttributeMaxDynamicSharedMemorySize, SMEM2);

    transpose_pb<<<dim3(V_DIM / 32, N_ADDR / 32), 256>>>(param_bank, pbt);

    score_gemm<<<dim3(N_ADDR / 64, M_TOT / 128), 256, SMEM1>>>(
        selector, address_space, w);

    softmax_rows<<<M_TOT, 256>>>(w, wh);

    out_gemm<<<dim3(V_DIM / 128, M_TOT / 128), 256, SMEM2>>>(wh, pbt, out);
}

// round 5
// speedup vs baseline: 6.0179x; 1.0597x over previous
#include <cuda_runtime.h>
#include <cuda_fp16.h>
#include <cstdint>

// SoftAddressSpace: out[M,V] = softmax(selector[M,D] @ AS[N,D]^T) @ PB[N,V]
// M=16384, D=128, N=4096, V=512, fp32 in/out.
// R4: fp16 HMMA everywhere.
//   GEMM1: hi/lo fp16 split (3 terms), CTA tile 128x128, all tiles smem-resident.
//   softmax: vectorized f32 -> fp16 weights.
//   GEMM2: plain fp16, 3-stage cp.async pipeline (unchanged from R3).

#define M_TOT  16384
#define N_ADDR 4096
#define D_DIM  128
#define V_DIM  512

static __device__ float  g_w  [(size_t)M_TOT * N_ADDR];   // f32 scores (256 MiB)
static __device__ __half g_wh [(size_t)M_TOT * N_ADDR];   // fp16 weights (128 MiB)
static __device__ __half g_pbt[(size_t)V_DIM * N_ADDR];   // fp16 PB^T (4 MiB)

__device__ __forceinline__ uint32_t smem_u32(const void* p) {
    uint32_t a;
    asm("{ .reg .u64 t; cvta.to.shared.u64 t, %1; cvt.u32.u64 %0, t; }" : "=r"(a) : "l"(p));
    return a;
}

#define LDSM_X4(r0, r1, r2, r3, addr) \
    asm volatile("ldmatrix.sync.aligned.m8n8.x4.shared.b16 {%0,%1,%2,%3}, [%4];" \
                 : "=r"(r0), "=r"(r1), "=r"(r2), "=r"(r3) : "r"(addr))

__device__ __forceinline__ void mma16816(float* d, const uint32_t* a, const uint32_t* b) {
    asm volatile(
        "mma.sync.aligned.m16n8k16.row.col.f32.f16.f16.f32 "
        "{%0,%1,%2,%3}, {%4,%5,%6,%7}, {%8,%9}, {%0,%1,%2,%3};"
        : "+f"(d[0]), "+f"(d[1]), "+f"(d[2]), "+f"(d[3])
        : "r"(a[0]), "r"(a[1]), "r"(a[2]), "r"(a[3]), "r"(b[0]), "r"(b[1]));
}

__device__ __forceinline__ void cp16(uint32_t dst, const void* src) {
    asm volatile("cp.async.cg.shared.global [%0], [%1], 16;" :: "r"(dst), "l"(src));
}
#define CP_COMMIT() asm volatile("cp.async.commit_group;" ::: "memory")
#define CP_WAIT1()  asm volatile("cp.async.wait_group 1;" ::: "memory")

// ---------------------------------------------------------------------------
// GEMM1: scores[M,N] = selector[M,128] @ AS[N,128]^T, hi/lo fp16 split.
// CTA tile 128x128, 8 warps (2m x 4n), warp tile 64x32.
// Smem: Ah @0, Al @32K, Bh @64K, Bl @96K (each 128 rows x 128 halves = 32KB).
// 256B rows, swizzle: off ^ (((off>>8)&7)<<4).
// ---------------------------------------------------------------------------
__global__ __launch_bounds__(256, 1) void score_gemm(
    const float* __restrict__ S, const float* __restrict__ AS,
    float* __restrict__ W)
{
    extern __shared__ char sm[];
    const uint32_t sb = smem_u32(sm);
    const int tid = threadIdx.x, lane = tid & 31, wid = tid >> 5;
    const int wm = wid & 1, wn = wid >> 1;
    const int m0 = blockIdx.y * 128, n0 = blockIdx.x * 128;

    auto cvt_store = [&](const float* src, uint32_t dh, uint32_t dl) {
        float4 v0 = *(const float4*)src, v1 = *(const float4*)(src + 4);
        float f[8] = {v0.x, v0.y, v0.z, v0.w, v1.x, v1.y, v1.z, v1.w};
        uint32_t hh[4], ll[4];
#pragma unroll
        for (int j = 0; j < 4; j++) {
            __half h0 = __float2half_rn(f[2 * j]);
            __half h1 = __float2half_rn(f[2 * j + 1]);
            __half l0 = __float2half_rn(f[2 * j]     - __half2float(h0));
            __half l1 = __float2half_rn(f[2 * j + 1] - __half2float(h1));
            __half2 hp = __halves2half2(h0, h1);
            __half2 lp = __halves2half2(l0, l1);
            hh[j] = *(uint32_t*)&hp;
            ll[j] = *(uint32_t*)&lp;
        }
        *(uint4*)(sm + dh) = make_uint4(hh[0], hh[1], hh[2], hh[3]);
        *(uint4*)(sm + dl) = make_uint4(ll[0], ll[1], ll[2], ll[3]);
    };

    // Load + convert A and B (each 128 rows x 128 f32)
#pragma unroll
    for (int s = 0; s < 8; s++) {
        int idx = tid + s * 256;            // 0..2047
        int r = idx >> 4, b = idx & 15;
        uint32_t off = (uint32_t)(r * 256 + b * 16);
        uint32_t sw = off ^ (((off >> 8) & 7) << 4);
        cvt_store(S + (size_t)(m0 + r) * D_DIM + b * 8, sw, 32768u + sw);
    }
#pragma unroll
    for (int s = 0; s < 8; s++) {
        int idx = tid + s * 256;
        int r = idx >> 4, b = idx & 15;
        uint32_t off = (uint32_t)(r * 256 + b * 16);
        uint32_t sw = off ^ (((off >> 8) & 7) << 4);
        cvt_store(AS + (size_t)(n0 + r) * D_DIM + b * 8, 65536u + sw, 98304u + sw);
    }
    __syncthreads();

    float acc[4][4][4];
#pragma unroll
    for (int i = 0; i < 4; i++)
#pragma unroll
        for (int j = 0; j < 4; j++)
#pragma unroll
            for (int k = 0; k < 4; k++) acc[i][j][k] = 0.0f;

    const int sub = lane >> 3, rr = lane & 7;

#pragma unroll
    for (int ks = 0; ks < 8; ks++) {
        uint32_t a[4][4], bh[8], bl[8];
        // Ah fragments
#pragma unroll
        for (int mf = 0; mf < 4; mf++) {
            int row = wm * 64 + mf * 16 + ((sub & 1) << 3) + rr;
            uint32_t off = (uint32_t)(row * 256 + ks * 32 + ((sub >> 1) << 4));
            uint32_t sw = off ^ (((off >> 8) & 7) << 4);
            LDSM_X4(a[mf][0], a[mf][1], a[mf][2], a[mf][3], sb + sw);
        }
        // Bh, Bl fragments
#pragma unroll
        for (int p = 0; p < 2; p++) {
            int nrow = wn * 32 + (p * 2 + (sub >> 1)) * 8 + rr;
            uint32_t off = (uint32_t)(nrow * 256 + ks * 32 + ((sub & 1) << 4));
            uint32_t sw = off ^ (((off >> 8) & 7) << 4);
            LDSM_X4(bh[p * 4], bh[p * 4 + 1], bh[p * 4 + 2], bh[p * 4 + 3], sb + 65536u + sw);
            LDSM_X4(bl[p * 4], bl[p * 4 + 1], bl[p * 4 + 2], bl[p * 4 + 3], sb + 98304u + sw);
        }
        // Ah*Bh + Ah*Bl
#pragma unroll
        for (int mf = 0; mf < 4; mf++)
#pragma unroll
            for (int nf = 0; nf < 4; nf++) {
                mma16816(acc[mf][nf], a[mf], &bh[nf * 2]);
                mma16816(acc[mf][nf], a[mf], &bl[nf * 2]);
            }
        // Al fragments (overwrite a), Al*Bh
#pragma unroll
        for (int mf = 0; mf < 4; mf++) {
            int row = wm * 64 + mf * 16 + ((sub & 1) << 3) + rr;
            uint32_t off = (uint32_t)(row * 256 + ks * 32 + ((sub >> 1) << 4));
            uint32_t sw = off ^ (((off >> 8) & 7) << 4);
            LDSM_X4(a[mf][0], a[mf][1], a[mf][2], a[mf][3], sb + 32768u + sw);
        }
#pragma unroll
        for (int mf = 0; mf < 4; mf++)
#pragma unroll
            for (int nf = 0; nf < 4; nf++)
                mma16816(acc[mf][nf], a[mf], &bh[nf * 2]);
    }

    const int lg = lane >> 2, lt = lane & 3;
#pragma unroll
    for (int mf = 0; mf < 4; mf++) {
        const int row = m0 + wm * 64 + mf * 16 + lg;
#pragma unroll
        for (int nf = 0; nf < 4; nf++) {
            const int col = n0 + wn * 32 + nf * 8 + lt * 2;
            *(float2*)(W + (size_t)row * N_ADDR + col) =
                make_float2(acc[mf][nf][0], acc[mf][nf][1]);
            *(float2*)(W + (size_t)(row + 8) * N_ADDR + col) =
                make_float2(acc[mf][nf][2], acc[mf][nf][3]);
        }
    }
}

// ---------------------------------------------------------------------------
// GEMM2: out[M,V] = Wh[M,4096] @ PBT[V,4096]^T, fp16 x fp16 -> fp32.
// CTA tile 128x128, 8 warps (2m x 4n), KC=64, cp.async 3-stage pipeline.
// ---------------------------------------------------------------------------
__global__ __launch_bounds__(256, 2) void out_gemm(
    const __half* __restrict__ Wh, const __half* __restrict__ PBT,
    float* __restrict__ C)
{
    extern __shared__ char sm[];
    const uint32_t sb = smem_u32(sm);
    const int tid = threadIdx.x, lane = tid & 31, wid = tid >> 5;
    const int wm = wid & 1, wn = wid >> 1;
    const int m0 = blockIdx.y * 128, n0 = blockIdx.x * 128;
    constexpr int CHUNKS = N_ADDR / 64;

    auto issue = [&](int st, int ci) {
        const uint32_t base = (uint32_t)st * 32768u;
        const int k0 = ci * 64;
#pragma unroll
        for (int s = 0; s < 4; s++) {
            int idx = tid + s * 256;        // 0..1023
            int r = idx >> 3, b = idx & 7;
            uint32_t off = (uint32_t)(r * 128 + b * 16);
            uint32_t sw = off ^ ((off >> 3) & 0x70);
            cp16(sb + base + sw,          Wh  + (size_t)(m0 + r) * N_ADDR + k0 + b * 8);
            cp16(sb + base + 16384 + sw,  PBT + (size_t)(n0 + r) * N_ADDR + k0 + b * 8);
        }
        CP_COMMIT();
    };

    float acc[4][4][4];
#pragma unroll
    for (int i = 0; i < 4; i++)
#pragma unroll
        for (int j = 0; j < 4; j++)
#pragma unroll
            for (int k = 0; k < 4; k++) acc[i][j][k] = 0.0f;

    issue(0, 0);
    issue(1, 1);

    const int sub = lane >> 3, rr = lane & 7;

    for (int ci = 0; ci < CHUNKS; ci++) {
        const int st = ci % 3;
        CP_WAIT1();
        __syncthreads();
        if (ci + 2 < CHUNKS) issue((ci + 2) % 3, ci + 2);

        const uint32_t ab = sb + (uint32_t)st * 32768u;
        const uint32_t bb = ab + 16384u;
#pragma unroll
        for (int ks = 0; ks < 4; ks++) {
            uint32_t a[4][4];
#pragma unroll
            for (int mf = 0; mf < 4; mf++) {
                int row = wm * 64 + mf * 16 + ((sub & 1) << 3) + rr;
                uint32_t off = (uint32_t)(row * 128 + ks * 32 + ((sub >> 1) << 4));
                uint32_t sw = off ^ ((off >> 3) & 0x70);
                LDSM_X4(a[mf][0], a[mf][1], a[mf][2], a[mf][3], ab + sw);
            }
            uint32_t bf[8];
#pragma unroll
            for (int p = 0; p < 2; p++) {
                int nrow = wn * 32 + (p * 2 + (sub >> 1)) * 8 + rr;
                uint32_t off = (uint32_t)(nrow * 128 + ks * 32 + ((sub & 1) << 4));
                uint32_t sw = off ^ ((off >> 3) & 0x70);
                LDSM_X4(bf[p * 4], bf[p * 4 + 1], bf[p * 4 + 2], bf[p * 4 + 3], bb + sw);
            }
#pragma unroll
            for (int mf = 0; mf < 4; mf++)
#pragma unroll
                for (int nf = 0; nf < 4; nf++)
                    mma16816(acc[mf][nf], a[mf], &bf[nf * 2]);
        }
    }

    const int lg = lane >> 2, lt = lane & 3;
#pragma unroll
    for (int mf = 0; mf < 4; mf++) {
        const int row = m0 + wm * 64 + mf * 16 + lg;
#pragma unroll
        for (int nf = 0; nf < 4; nf++) {
            const int col = n0 + wn * 32 + nf * 8 + lt * 2;
            *(float2*)(C + (size_t)row * V_DIM + col) =
                make_float2(acc[mf][nf][0], acc[mf][nf][1]);
            *(float2*)(C + (size_t)(row + 8) * V_DIM + col) =
                make_float2(acc[mf][nf][2], acc[mf][nf][3]);
        }
    }
}

// ---------------------------------------------------------------------------
// Row softmax: f32 scores -> fp16 weights. One CTA (256 thr) per row.
// float4 loads for MLP; vectorized fp16 stores.
// ---------------------------------------------------------------------------
__global__ __launch_bounds__(256) void softmax_rows(
    const float* __restrict__ W, __half* __restrict__ Wh)
{
    const int row = blockIdx.x;
    const float4* p = (const float4*)(W + (size_t)row * N_ADDR);
    const int tid = threadIdx.x;

    float4 v[4];
    float mx = -1e30f;
#pragma unroll
    for (int i = 0; i < 4; i++) {
        v[i] = p[tid + i * 256];
        mx = fmaxf(mx, fmaxf(fmaxf(v[i].x, v[i].y), fmaxf(v[i].z, v[i].w)));
    }
#pragma unroll
    for (int o = 16; o; o >>= 1) mx = fmaxf(mx, __shfl_xor_sync(0xffffffffu, mx, o));
    __shared__ float smx[8], ssm[8];
    if ((tid & 31) == 0) smx[tid >> 5] = mx;
    __syncthreads();
    mx = smx[0];
#pragma unroll
    for (int i = 1; i < 8; i++) mx = fmaxf(mx, smx[i]);

    float s = 0.0f;
#pragma unroll
    for (int i = 0; i < 4; i++) {
        v[i].x = __expf(v[i].x - mx);
        v[i].y = __expf(v[i].y - mx);
        v[i].z = __expf(v[i].z - mx);
        v[i].w = __expf(v[i].w - mx);
        s += (v[i].x + v[i].y) + (v[i].z + v[i].w);
    }
#pragma unroll
    for (int o = 16; o; o >>= 1) s += __shfl_xor_sync(0xffffffffu, s, o);
    if ((tid & 31) == 0) ssm[tid >> 5] = s;
    __syncthreads();
    s = 0.0f;
#pragma unroll
    for (int i = 0; i < 8; i++) s += ssm[i];

    const float inv = 1.0f / s;
    uint2* q = (uint2*)(Wh + (size_t)row * N_ADDR);
#pragma unroll
    for (int i = 0; i < 4; i++) {
        __half2 h0 = __floats2half2_rn(v[i].x * inv, v[i].y * inv);
        __half2 h1 = __floats2half2_rn(v[i].z * inv, v[i].w * inv);
        q[tid + i * 256] = make_uint2(*(uint32_t*)&h0, *(uint32_t*)&h1);
    }
}

// ---------------------------------------------------------------------------
// param_bank [N,V] f32 -> PBT [V,N] fp16
// ---------------------------------------------------------------------------
__global__ __launch_bounds__(256) void transpose_pb(
    const float* __restrict__ PB, __half* __restrict__ PBT)
{
    __shared__ float t[32][33];
    const int bx = blockIdx.x * 32;  // V
    const int by = blockIdx.y * 32;  // N
    const int x = threadIdx.x & 31;
    const int y = threadIdx.x >> 5;  // 0..7
#pragma unroll
    for (int j = 0; j < 32; j += 8)
        t[y + j][x] = PB[(size_t)(by + y + j) * V_DIM + bx + x];
    __syncthreads();
#pragma unroll
    for (int j = 0; j < 32; j += 8)
        PBT[(size_t)(bx + y + j) * N_ADDR + by + x] = __float2half_rn(t[x][y + j]);
}

// ---------------------------------------------------------------------------
extern "C" void kernel_launch(void* const* d_in, const int* in_sizes, int n_in,
                              void* d_out, int out_size)
{
    const float* selector      = (const float*)d_in[0];  // [16384, 128]
    const float* param_bank    = (const float*)d_in[1];  // [4096, 512]
    const float* address_space = (const float*)d_in[2];  // [4096, 128]
    float* out = (float*)d_out;                          // [16384, 512]

    float*  w;   cudaGetSymbolAddress((void**)&w,   g_w);
    __half* wh;  cudaGetSymbolAddress((void**)&wh,  g_wh);
    __half* pbt; cudaGetSymbolAddress((void**)&pbt, g_pbt);

    constexpr uint32_t SMEM1 = 131072;  // 128KB (Ah+Al+Bh+Bl, 32KB each)
    constexpr uint32_t SMEM2 = 98304;   // 96KB (3 x 32KB stages)
    cudaFuncSetAttribute(score_gemm, cudaFuncAttributeMaxDynamicSharedMemorySize, SMEM1);
    cudaFuncSetAttribute(out_gemm,   cudaFuncAttributeMaxDynamicSharedMemorySize, SMEM2);

    transpose_pb<<<dim3(V_DIM / 32, N_ADDR / 32), 256>>>(param_bank, pbt);

    score_gemm<<<dim3(N_ADDR / 128, M_TOT / 128), 256, SMEM1>>>(
        selector, address_space, w);

    softmax_rows<<<M_TOT, 256>>>(w, wh);

    out_gemm<<<dim3(V_DIM / 128, M_TOT / 128), 256, SMEM2>>>(wh, pbt, out);
}

// round 6
// speedup vs baseline: 6.3224x; 1.0506x over previous
#include <cuda_runtime.h>
#include <cuda_fp16.h>
#include <cstdint>

// SoftAddressSpace: out[M,V] = softmax(selector[M,D] @ AS[N,D]^T) @ PB[N,V]
// M=16384, D=128, N=4096, V=512, fp32 in/out.
// R5: FlashDecoding-style 2-pass split.
//   prep:  AS -> hi/lo fp16; PB -> fp16 PB^T.
//   pass1: per-128-row strip: scores (3-term fp16 split HMMA) + ONLINE softmax,
//          stores p=exp(s-m_run) fp16, per-(row,tile) rescale r, and 1/sum.
//   pass2: out = (P @ PBT^T) with flash rescale per k-tile, final *1/sum.

#define M_TOT  16384
#define N_ADDR 4096
#define D_DIM  128
#define V_DIM  512
#define NTILES (N_ADDR / 128)   // 32

static __device__ __half g_p   [(size_t)M_TOT * N_ADDR];   // fp16 p (128 MiB)
static __device__ __half g_pbt [(size_t)V_DIM * N_ADDR];   // fp16 PB^T (4 MiB)
static __device__ __half g_ash [(size_t)N_ADDR * D_DIM];   // AS hi (1 MiB)
static __device__ __half g_asl [(size_t)N_ADDR * D_DIM];   // AS lo (1 MiB)
static __device__ float  g_r   [(size_t)M_TOT * NTILES];   // rescale factors (2 MiB)
static __device__ float  g_sinv[(size_t)M_TOT];            // 1/sum per row

__device__ __forceinline__ uint32_t smem_u32(const void* p) {
    uint32_t a;
    asm("{ .reg .u64 t; cvta.to.shared.u64 t, %1; cvt.u32.u64 %0, t; }" : "=r"(a) : "l"(p));
    return a;
}

#define LDSM_X4(r0, r1, r2, r3, addr) \
    asm volatile("ldmatrix.sync.aligned.m8n8.x4.shared.b16 {%0,%1,%2,%3}, [%4];" \
                 : "=r"(r0), "=r"(r1), "=r"(r2), "=r"(r3) : "r"(addr))

__device__ __forceinline__ void mma16816(float* d, const uint32_t* a, const uint32_t* b) {
    asm volatile(
        "mma.sync.aligned.m16n8k16.row.col.f32.f16.f16.f32 "
        "{%0,%1,%2,%3}, {%4,%5,%6,%7}, {%8,%9}, {%0,%1,%2,%3};"
        : "+f"(d[0]), "+f"(d[1]), "+f"(d[2]), "+f"(d[3])
        : "r"(a[0]), "r"(a[1]), "r"(a[2]), "r"(a[3]), "r"(b[0]), "r"(b[1]));
}

__device__ __forceinline__ void cp16(uint32_t dst, const void* src) {
    asm volatile("cp.async.cg.shared.global [%0], [%1], 16;" :: "r"(dst), "l"(src));
}
#define CP_COMMIT() asm volatile("cp.async.commit_group;" ::: "memory")
#define CP_WAIT1()  asm volatile("cp.async.wait_group 1;" ::: "memory")
#define CP_WAIT0()  asm volatile("cp.async.wait_group 0;" ::: "memory")

// ---------------------------------------------------------------------------
// Pass 1: persistent strip kernel. Grid = 128 CTAs, each owns 128 M-rows.
// Smem: Sh @0 (32KB), Sl @32K, B stages @64K: 2 x [Bh 32K | Bl 32K].
// 256B smem rows; swizzle off ^ (((off>>8)&7)<<4).
// ---------------------------------------------------------------------------
__global__ __launch_bounds__(256, 1) void score_pass(
    const float* __restrict__ S,
    const __half* __restrict__ ASh, const __half* __restrict__ ASl,
    __half* __restrict__ P, float* __restrict__ R, float* __restrict__ SINV)
{
    extern __shared__ char sm[];
    __shared__ float redbuf[2][2][64][4];   // [buf][wm][row64][wn]
    const uint32_t sb = smem_u32(sm);
    const int tid = threadIdx.x, lane = tid & 31, wid = tid >> 5;
    const int wm = wid & 1, wn = wid >> 1;
    const int m0 = blockIdx.x * 128;
    const int sub = lane >> 3, rr = lane & 7;
    const int lg = lane >> 2, lt = lane & 3;

    // --- load + hi/lo convert selector strip (resident) ---
#pragma unroll
    for (int s = 0; s < 8; s++) {
        int idx = tid + s * 256;            // 0..2047
        int r = idx >> 4, b = idx & 15;
        uint32_t off = (uint32_t)(r * 256 + b * 16);
        uint32_t sw = off ^ (((off >> 8) & 7) << 4);
        const float* src = S + (size_t)(m0 + r) * D_DIM + b * 8;
        float4 v0 = *(const float4*)src, v1 = *(const float4*)(src + 4);
        float f[8] = {v0.x, v0.y, v0.z, v0.w, v1.x, v1.y, v1.z, v1.w};
        uint32_t hh[4], ll[4];
#pragma unroll
        for (int j = 0; j < 4; j++) {
            __half h0 = __float2half_rn(f[2 * j]);
            __half h1 = __float2half_rn(f[2 * j + 1]);
            __half l0 = __float2half_rn(f[2 * j]     - __half2float(h0));
            __half l1 = __float2half_rn(f[2 * j + 1] - __half2float(h1));
            __half2 hp = __halves2half2(h0, h1);
            __half2 lp = __halves2half2(l0, l1);
            hh[j] = *(uint32_t*)&hp; ll[j] = *(uint32_t*)&lp;
        }
        *(uint4*)(sm + sw)          = make_uint4(hh[0], hh[1], hh[2], hh[3]);
        *(uint4*)(sm + 32768u + sw) = make_uint4(ll[0], ll[1], ll[2], ll[3]);
    }

    auto issueB = [&](int st, int t) {
        const uint32_t base = 65536u + (uint32_t)st * 65536u;
#pragma unroll
        for (int s = 0; s < 8; s++) {
            int idx = tid + s * 256;        // 0..2047
            int r = idx >> 4, b = idx & 15;
            uint32_t off = (uint32_t)(r * 256 + b * 16);
            uint32_t sw = off ^ (((off >> 8) & 7) << 4);
            const size_t go = (size_t)(t * 128 + r) * D_DIM + b * 8;
            cp16(sb + base + sw,          ASh + go);
            cp16(sb + base + 32768u + sw, ASl + go);
        }
        CP_COMMIT();
    };

    issueB(0, 0);

    float m_run[4][2], s_run[4][2];
#pragma unroll
    for (int mf = 0; mf < 4; mf++) { m_run[mf][0] = m_run[mf][1] = -1e30f; s_run[mf][0] = s_run[mf][1] = 0.0f; }

    for (int t = 0; t < NTILES; t++) {
        __syncthreads();                      // everyone done with stage (t+1)&1
        if (t + 1 < NTILES) { issueB((t + 1) & 1, t + 1); CP_WAIT1(); }
        else                { CP_WAIT0(); }
        __syncthreads();

        const uint32_t bbase = sb + 65536u + (uint32_t)(t & 1) * 65536u;

        float acc[4][4][4];
#pragma unroll
        for (int i = 0; i < 4; i++)
#pragma unroll
            for (int j = 0; j < 4; j++)
#pragma unroll
                for (int k = 0; k < 4; k++) acc[i][j][k] = 0.0f;

#pragma unroll
        for (int ks = 0; ks < 8; ks++) {
            uint32_t a[4][4], bh[8], bl[8];
#pragma unroll
            for (int mf = 0; mf < 4; mf++) {
                int row = wm * 64 + mf * 16 + ((sub & 1) << 3) + rr;
                uint32_t off = (uint32_t)(row * 256 + ks * 32 + ((sub >> 1) << 4));
                uint32_t sw = off ^ (((off >> 8) & 7) << 4);
                LDSM_X4(a[mf][0], a[mf][1], a[mf][2], a[mf][3], sb + sw);
            }
#pragma unroll
            for (int p2 = 0; p2 < 2; p2++) {
                int nrow = wn * 32 + (p2 * 2 + (sub >> 1)) * 8 + rr;
                uint32_t off = (uint32_t)(nrow * 256 + ks * 32 + ((sub & 1) << 4));
                uint32_t sw = off ^ (((off >> 8) & 7) << 4);
                LDSM_X4(bh[p2 * 4], bh[p2 * 4 + 1], bh[p2 * 4 + 2], bh[p2 * 4 + 3], bbase + sw);
                LDSM_X4(bl[p2 * 4], bl[p2 * 4 + 1], bl[p2 * 4 + 2], bl[p2 * 4 + 3], bbase + 32768u + sw);
            }
#pragma unroll
            for (int mf = 0; mf < 4; mf++)
#pragma unroll
                for (int nf = 0; nf < 4; nf++) {
                    mma16816(acc[mf][nf], a[mf], &bh[nf * 2]);
                    mma16816(acc[mf][nf], a[mf], &bl[nf * 2]);
                }
#pragma unroll
            for (int mf = 0; mf < 4; mf++) {
                int row = wm * 64 + mf * 16 + ((sub & 1) << 3) + rr;
                uint32_t off = (uint32_t)(row * 256 + ks * 32 + ((sub >> 1) << 4));
                uint32_t sw = off ^ (((off >> 8) & 7) << 4);
                LDSM_X4(a[mf][0], a[mf][1], a[mf][2], a[mf][3], sb + 32768u + sw);
            }
#pragma unroll
            for (int mf = 0; mf < 4; mf++)
#pragma unroll
                for (int nf = 0; nf < 4; nf++)
                    mma16816(acc[mf][nf], a[mf], &bh[nf * 2]);
        }

        // --- online softmax stats ---
        float tmx[4][2];
#pragma unroll
        for (int mf = 0; mf < 4; mf++)
#pragma unroll
            for (int h = 0; h < 2; h++) {
                float v = -1e30f;
#pragma unroll
                for (int nf = 0; nf < 4; nf++)
                    v = fmaxf(v, fmaxf(acc[mf][nf][2 * h], acc[mf][nf][2 * h + 1]));
                v = fmaxf(v, __shfl_xor_sync(0xffffffffu, v, 1));
                v = fmaxf(v, __shfl_xor_sync(0xffffffffu, v, 2));
                tmx[mf][h] = v;
                if (lt == 0) redbuf[0][wm][mf * 16 + lg + 8 * h][wn] = v;
            }
        __syncthreads();

        float mnew[4][2], rfac[4][2], tsum[4][2];
#pragma unroll
        for (int mf = 0; mf < 4; mf++)
#pragma unroll
            for (int h = 0; h < 2; h++) {
                const int r64 = mf * 16 + lg + 8 * h;
                float tm = fmaxf(fmaxf(redbuf[0][wm][r64][0], redbuf[0][wm][r64][1]),
                                 fmaxf(redbuf[0][wm][r64][2], redbuf[0][wm][r64][3]));
                float mn = fmaxf(m_run[mf][h], tm);
                mnew[mf][h] = mn;
                rfac[mf][h] = __expf(m_run[mf][h] - mn);
                s_run[mf][h] *= rfac[mf][h];
                tsum[mf][h] = 0.0f;
            }
#pragma unroll
        for (int mf = 0; mf < 4; mf++)
#pragma unroll
            for (int nf = 0; nf < 4; nf++) {
                acc[mf][nf][0] = __expf(acc[mf][nf][0] - mnew[mf][0]);
                acc[mf][nf][1] = __expf(acc[mf][nf][1] - mnew[mf][0]);
                acc[mf][nf][2] = __expf(acc[mf][nf][2] - mnew[mf][1]);
                acc[mf][nf][3] = __expf(acc[mf][nf][3] - mnew[mf][1]);
                tsum[mf][0] += acc[mf][nf][0] + acc[mf][nf][1];
                tsum[mf][1] += acc[mf][nf][2] + acc[mf][nf][3];
            }
#pragma unroll
        for (int mf = 0; mf < 4; mf++)
#pragma unroll
            for (int h = 0; h < 2; h++) {
                float v = tsum[mf][h];
                v += __shfl_xor_sync(0xffffffffu, v, 1);
                v += __shfl_xor_sync(0xffffffffu, v, 2);
                if (lt == 0) redbuf[1][wm][mf * 16 + lg + 8 * h][wn] = v;
            }
        __syncthreads();
#pragma unroll
        for (int mf = 0; mf < 4; mf++)
#pragma unroll
            for (int h = 0; h < 2; h++) {
                const int r64 = mf * 16 + lg + 8 * h;
                s_run[mf][h] += (redbuf[1][wm][r64][0] + redbuf[1][wm][r64][1]) +
                                (redbuf[1][wm][r64][2] + redbuf[1][wm][r64][3]);
                m_run[mf][h] = mnew[mf][h];
            }

        // --- store p tile (fp16) and r factors ---
#pragma unroll
        for (int mf = 0; mf < 4; mf++) {
            const int row = m0 + wm * 64 + mf * 16 + lg;
#pragma unroll
            for (int nf = 0; nf < 4; nf++) {
                const int col = t * 128 + wn * 32 + nf * 8 + lt * 2;
                __half2 p0 = __floats2half2_rn(acc[mf][nf][0], acc[mf][nf][1]);
                __half2 p1 = __floats2half2_rn(acc[mf][nf][2], acc[mf][nf][3]);
                *(__half2*)(P + (size_t)row * N_ADDR + col)       = p0;
                *(__half2*)(P + (size_t)(row + 8) * N_ADDR + col) = p1;
            }
        }
        if (wn == 0 && lt == 0) {
#pragma unroll
            for (int mf = 0; mf < 4; mf++)
#pragma unroll
                for (int h = 0; h < 2; h++) {
                    const int row = m0 + wm * 64 + mf * 16 + lg + 8 * h;
                    R[(size_t)row * NTILES + t] = rfac[mf][h];
                }
        }
    }

    if (wn == 0 && lt == 0) {
#pragma unroll
        for (int mf = 0; mf < 4; mf++)
#pragma unroll
            for (int h = 0; h < 2; h++) {
                const int row = m0 + wm * 64 + mf * 16 + lg + 8 * h;
                SINV[row] = 1.0f / s_run[mf][h];
            }
    }
}

// ---------------------------------------------------------------------------
// Pass 2: out[M,V] = (P @ PBT^T) with per-k-tile flash rescale.
// CTA tile 128x128, 8 warps, KC=64, cp.async 3-stage pipeline.
// ---------------------------------------------------------------------------
__global__ __launch_bounds__(256, 2) void out_gemm(
    const __half* __restrict__ P, const __half* __restrict__ PBT,
    float* __restrict__ C,
    const float* __restrict__ R, const float* __restrict__ SINV)
{
    extern __shared__ char sm[];
    const uint32_t sb = smem_u32(sm);
    const int tid = threadIdx.x, lane = tid & 31, wid = tid >> 5;
    const int wm = wid & 1, wn = wid >> 1;
    const int m0 = blockIdx.y * 128, n0 = blockIdx.x * 128;
    constexpr int CHUNKS = N_ADDR / 64;
    const int sub = lane >> 3, rr = lane & 7;
    const int lg = lane >> 2, lt = lane & 3;

    int rowg[4][2];
#pragma unroll
    for (int mf = 0; mf < 4; mf++)
#pragma unroll
        for (int h = 0; h < 2; h++)
            rowg[mf][h] = m0 + wm * 64 + mf * 16 + lg + 8 * h;

    auto issue = [&](int st, int ci) {
        const uint32_t base = (uint32_t)st * 32768u;
        const int k0 = ci * 64;
#pragma unroll
        for (int s = 0; s < 4; s++) {
            int idx = tid + s * 256;
            int r = idx >> 3, b = idx & 7;
            uint32_t off = (uint32_t)(r * 128 + b * 16);
            uint32_t sw = off ^ ((off >> 3) & 0x70);
            cp16(sb + base + sw,          P   + (size_t)(m0 + r) * N_ADDR + k0 + b * 8);
            cp16(sb + base + 16384 + sw,  PBT + (size_t)(n0 + r) * N_ADDR + k0 + b * 8);
        }
        CP_COMMIT();
    };

    float acc[4][4][4];
#pragma unroll
    for (int i = 0; i < 4; i++)
#pragma unroll
        for (int j = 0; j < 4; j++)
#pragma unroll
            for (int k = 0; k < 4; k++) acc[i][j][k] = 0.0f;

    issue(0, 0);
    issue(1, 1);

    for (int ci = 0; ci < CHUNKS; ci++) {
        const int st = ci % 3;
        CP_WAIT1();
        __syncthreads();
        if (ci + 2 < CHUNKS) issue((ci + 2) % 3, ci + 2);

        if ((ci & 1) == 0) {            // flash rescale at each 128-wide k-tile
            const int t = ci >> 1;
            float rv[4][2];
#pragma unroll
            for (int mf = 0; mf < 4; mf++)
#pragma unroll
                for (int h = 0; h < 2; h++)
                    rv[mf][h] = __ldg(R + (size_t)rowg[mf][h] * NTILES + t);
#pragma unroll
            for (int mf = 0; mf < 4; mf++)
#pragma unroll
                for (int nf = 0; nf < 4; nf++) {
                    acc[mf][nf][0] *= rv[mf][0];
                    acc[mf][nf][1] *= rv[mf][0];
                    acc[mf][nf][2] *= rv[mf][1];
                    acc[mf][nf][3] *= rv[mf][1];
                }
        }

        const uint32_t ab = sb + (uint32_t)st * 32768u;
        const uint32_t bb = ab + 16384u;
#pragma unroll
        for (int ks = 0; ks < 4; ks++) {
            uint32_t a[4][4];
#pragma unroll
            for (int mf = 0; mf < 4; mf++) {
                int row = wm * 64 + mf * 16 + ((sub & 1) << 3) + rr;
                uint32_t off = (uint32_t)(row * 128 + ks * 32 + ((sub >> 1) << 4));
                uint32_t sw = off ^ ((off >> 3) & 0x70);
                LDSM_X4(a[mf][0], a[mf][1], a[mf][2], a[mf][3], ab + sw);
            }
            uint32_t bf[8];
#pragma unroll
            for (int p2 = 0; p2 < 2; p2++) {
                int nrow = wn * 32 + (p2 * 2 + (sub >> 1)) * 8 + rr;
                uint32_t off = (uint32_t)(nrow * 128 + ks * 32 + ((sub & 1) << 4));
                uint32_t sw = off ^ ((off >> 3) & 0x70);
                LDSM_X4(bf[p2 * 4], bf[p2 * 4 + 1], bf[p2 * 4 + 2], bf[p2 * 4 + 3], bb + sw);
            }
#pragma unroll
            for (int mf = 0; mf < 4; mf++)
#pragma unroll
                for (int nf = 0; nf < 4; nf++)
                    mma16816(acc[mf][nf], a[mf], &bf[nf * 2]);
        }
    }

#pragma unroll
    for (int mf = 0; mf < 4; mf++) {
        const float s0 = __ldg(SINV + rowg[mf][0]);
        const float s1 = __ldg(SINV + rowg[mf][1]);
#pragma unroll
        for (int nf = 0; nf < 4; nf++) {
            const int col = n0 + wn * 32 + nf * 8 + lt * 2;
            *(float2*)(C + (size_t)rowg[mf][0] * V_DIM + col) =
                make_float2(acc[mf][nf][0] * s0, acc[mf][nf][1] * s0);
            *(float2*)(C + (size_t)rowg[mf][1] * V_DIM + col) =
                make_float2(acc[mf][nf][2] * s1, acc[mf][nf][3] * s1);
        }
    }
}

// ---------------------------------------------------------------------------
// Prep: AS f32 -> hi/lo fp16 arrays.
// ---------------------------------------------------------------------------
__global__ __launch_bounds__(256) void convert_as(
    const float* __restrict__ AS, __half* __restrict__ Hh, __half* __restrict__ Hl)
{
    const int i = blockIdx.x * 256 + threadIdx.x;   // each handles 8 floats
    const float4 v0 = ((const float4*)AS)[i * 2];
    const float4 v1 = ((const float4*)AS)[i * 2 + 1];
    float f[8] = {v0.x, v0.y, v0.z, v0.w, v1.x, v1.y, v1.z, v1.w};
    uint32_t hh[4], ll[4];
#pragma unroll
    for (int j = 0; j < 4; j++) {
        __half h0 = __float2half_rn(f[2 * j]);
        __half h1 = __float2half_rn(f[2 * j + 1]);
        __half l0 = __float2half_rn(f[2 * j]     - __half2float(h0));
        __half l1 = __float2half_rn(f[2 * j + 1] - __half2float(h1));
        __half2 hp = __halves2half2(h0, h1);
        __half2 lp = __halves2half2(l0, l1);
        hh[j] = *(uint32_t*)&hp; ll[j] = *(uint32_t*)&lp;
    }
    ((uint4*)Hh)[i] = make_uint4(hh[0], hh[1], hh[2], hh[3]);
    ((uint4*)Hl)[i] = make_uint4(ll[0], ll[1], ll[2], ll[3]);
}

// ---------------------------------------------------------------------------
// param_bank [N,V] f32 -> PBT [V,N] fp16
// ---------------------------------------------------------------------------
__global__ __launch_bounds__(256) void transpose_pb(
    const float* __restrict__ PB, __half* __restrict__ PBT)
{
    __shared__ float t[32][33];
    const int bx = blockIdx.x * 32;  // V
    const int by = blockIdx.y * 32;  // N
    const int x = threadIdx.x & 31;
    const int y = threadIdx.x >> 5;
#pragma unroll
    for (int j = 0; j < 32; j += 8)
        t[y + j][x] = PB[(size_t)(by + y + j) * V_DIM + bx + x];
    __syncthreads();
#pragma unroll
    for (int j = 0; j < 32; j += 8)
        PBT[(size_t)(bx + y + j) * N_ADDR + by + x] = __float2half_rn(t[x][y + j]);
}

// ---------------------------------------------------------------------------
extern "C" void kernel_launch(void* const* d_in, const int* in_sizes, int n_in,
                              void* d_out, int out_size)
{
    const float* selector      = (const float*)d_in[0];  // [16384, 128]
    const float* param_bank    = (const float*)d_in[1];  // [4096, 512]
    const float* address_space = (const float*)d_in[2];  // [4096, 128]
    float* out = (float*)d_out;                          // [16384, 512]

    __half* p;    cudaGetSymbolAddress((void**)&p,    g_p);
    __half* pbt;  cudaGetSymbolAddress((void**)&pbt,  g_pbt);
    __half* ash;  cudaGetSymbolAddress((void**)&ash,  g_ash);
    __half* asl;  cudaGetSymbolAddress((void**)&asl,  g_asl);
    float*  rbuf; cudaGetSymbolAddress((void**)&rbuf, g_r);
    float*  sinv; cudaGetSymbolAddress((void**)&sinv, g_sinv);

    constexpr uint32_t SMEM1 = 196608;  // Sh+Sl (64K) + 2 B-stages (128K)
    constexpr uint32_t SMEM2 = 98304;   // 3 x 32KB stages
    cudaFuncSetAttribute(score_pass, cudaFuncAttributeMaxDynamicSharedMemorySize, SMEM1);
    cudaFuncSetAttribute(out_gemm,   cudaFuncAttributeMaxDynamicSharedMemorySize, SMEM2);

    transpose_pb<<<dim3(V_DIM / 32, N_ADDR / 32), 256>>>(param_bank, pbt);
    convert_as<<<(N_ADDR * D_DIM / 8) / 256, 256>>>(address_space, ash, asl);

    score_pass<<<M_TOT / 128, 256, SMEM1>>>(selector, ash, asl, p, rbuf, sinv);

    out_gemm<<<dim3(V_DIM / 128, M_TOT / 128), 256, SMEM2>>>(p, pbt, out, rbuf, sinv);
}

// round 7
// speedup vs baseline: 6.5528x; 1.0364x over previous
#include <cuda_runtime.h>
#include <cuda_fp16.h>
#include <cstdint>

// SoftAddressSpace: out[M,V] = softmax(selector[M,D] @ AS[N,D]^T) @ PB[N,V]
// M=16384, D=128, N=4096, V=512, fp32 in/out.
// R6: flash 2-pass, refined.
//   pass1: warp-owns-rows (16x128 warp tile) -> warp-local online softmax,
//          1 syncthreads per tile; stores p fp16 + R[t][row] + 1/sum.
//   pass2: out gemm with PREFETCHED rescale factors (R in [t][row] layout).

#define M_TOT  16384
#define N_ADDR 4096
#define D_DIM  128
#define V_DIM  512
#define NTILES (N_ADDR / 128)   // 32

static __device__ __half g_p   [(size_t)M_TOT * N_ADDR];   // fp16 p (128 MiB)
static __device__ __half g_pbt [(size_t)V_DIM * N_ADDR];   // fp16 PB^T (4 MiB)
static __device__ __half g_ash [(size_t)N_ADDR * D_DIM];   // AS hi (1 MiB)
static __device__ __half g_asl [(size_t)N_ADDR * D_DIM];   // AS lo (1 MiB)
static __device__ float  g_r   [(size_t)NTILES * M_TOT];   // rescale, [t][row]
static __device__ float  g_sinv[(size_t)M_TOT];            // 1/sum per row

__device__ __forceinline__ uint32_t smem_u32(const void* p) {
    uint32_t a;
    asm("{ .reg .u64 t; cvta.to.shared.u64 t, %1; cvt.u32.u64 %0, t; }" : "=r"(a) : "l"(p));
    return a;
}

#define LDSM_X4(r0, r1, r2, r3, addr) \
    asm volatile("ldmatrix.sync.aligned.m8n8.x4.shared.b16 {%0,%1,%2,%3}, [%4];" \
                 : "=r"(r0), "=r"(r1), "=r"(r2), "=r"(r3) : "r"(addr))

__device__ __forceinline__ void mma16816(float* d, const uint32_t* a, const uint32_t* b) {
    asm volatile(
        "mma.sync.aligned.m16n8k16.row.col.f32.f16.f16.f32 "
        "{%0,%1,%2,%3}, {%4,%5,%6,%7}, {%8,%9}, {%0,%1,%2,%3};"
        : "+f"(d[0]), "+f"(d[1]), "+f"(d[2]), "+f"(d[3])
        : "r"(a[0]), "r"(a[1]), "r"(a[2]), "r"(a[3]), "r"(b[0]), "r"(b[1]));
}

__device__ __forceinline__ void cp16(uint32_t dst, const void* src) {
    asm volatile("cp.async.cg.shared.global [%0], [%1], 16;" :: "r"(dst), "l"(src));
}
#define CP_COMMIT() asm volatile("cp.async.commit_group;" ::: "memory")
#define CP_WAIT1()  asm volatile("cp.async.wait_group 1;" ::: "memory")
#define CP_WAIT0()  asm volatile("cp.async.wait_group 0;" ::: "memory")

// ---------------------------------------------------------------------------
// Pass 1: grid = 128 CTAs, each owns a 128-row strip; warp w owns rows
// [w*16, w*16+16). Smem: Sh @0 (32K), Sl @32K, B stages @64K (2 x [Bh|Bl] 64K).
// 256B smem rows; swizzle off ^ (((off>>8)&7)<<4). One syncthreads per tile.
// ---------------------------------------------------------------------------
__global__ __launch_bounds__(256, 1) void score_pass(
    const float* __restrict__ S,
    const __half* __restrict__ ASh, const __half* __restrict__ ASl,
    __half* __restrict__ P, float* __restrict__ R, float* __restrict__ SINV)
{
    extern __shared__ char sm[];
    const uint32_t sb = smem_u32(sm);
    const int tid = threadIdx.x, lane = tid & 31, wid = tid >> 5;
    const int m0 = blockIdx.x * 128;
    const int sub = lane >> 3, rr = lane & 7;
    const int lg = lane >> 2, lt = lane & 3;
    const int wrow = wid * 16;                  // warp's row base within strip

    // --- load + hi/lo convert selector strip (resident) ---
#pragma unroll
    for (int s = 0; s < 8; s++) {
        int idx = tid + s * 256;                // 0..2047
        int r = idx >> 4, b = idx & 15;
        uint32_t off = (uint32_t)(r * 256 + b * 16);
        uint32_t sw = off ^ (((off >> 8) & 7) << 4);
        const float* src = S + (size_t)(m0 + r) * D_DIM + b * 8;
        float4 v0 = *(const float4*)src, v1 = *(const float4*)(src + 4);
        float f[8] = {v0.x, v0.y, v0.z, v0.w, v1.x, v1.y, v1.z, v1.w};
        uint32_t hh[4], ll[4];
#pragma unroll
        for (int j = 0; j < 4; j++) {
            __half h0 = __float2half_rn(f[2 * j]);
            __half h1 = __float2half_rn(f[2 * j + 1]);
            __half l0 = __float2half_rn(f[2 * j]     - __half2float(h0));
            __half l1 = __float2half_rn(f[2 * j + 1] - __half2float(h1));
            __half2 hp = __halves2half2(h0, h1);
            __half2 lp = __halves2half2(l0, l1);
            hh[j] = *(uint32_t*)&hp; ll[j] = *(uint32_t*)&lp;
        }
        *(uint4*)(sm + sw)          = make_uint4(hh[0], hh[1], hh[2], hh[3]);
        *(uint4*)(sm + 32768u + sw) = make_uint4(ll[0], ll[1], ll[2], ll[3]);
    }

    auto issueB = [&](int st, int t) {
        const uint32_t base = 65536u + (uint32_t)st * 65536u;
#pragma unroll
        for (int s = 0; s < 8; s++) {
            int idx = tid + s * 256;
            int r = idx >> 4, b = idx & 15;
            uint32_t off = (uint32_t)(r * 256 + b * 16);
            uint32_t sw = off ^ (((off >> 8) & 7) << 4);
            const size_t go = (size_t)(t * 128 + r) * D_DIM + b * 8;
            cp16(sb + base + sw,          ASh + go);
            cp16(sb + base + 32768u + sw, ASl + go);
        }
        CP_COMMIT();
    };

    issueB(0, 0);

    float m_run[2] = {-1e30f, -1e30f}, s_run[2] = {0.0f, 0.0f};

    for (int t = 0; t < NTILES; t++) {
        CP_WAIT0();
        __syncthreads();
        if (t + 1 < NTILES) issueB((t + 1) & 1, t + 1);

        const uint32_t bbase = sb + 65536u + (uint32_t)(t & 1) * 65536u;

        float acc[16][4];
#pragma unroll
        for (int i = 0; i < 16; i++)
#pragma unroll
            for (int k = 0; k < 4; k++) acc[i][k] = 0.0f;

#pragma unroll
        for (int ks = 0; ks < 8; ks++) {
            uint32_t ah[4], al[4], bh[32], bl[32];
            {
                int row = wrow + ((sub & 1) << 3) + rr;
                uint32_t off = (uint32_t)(row * 256 + ks * 32 + ((sub >> 1) << 4));
                uint32_t sw = off ^ (((off >> 8) & 7) << 4);
                LDSM_X4(ah[0], ah[1], ah[2], ah[3], sb + sw);
                LDSM_X4(al[0], al[1], al[2], al[3], sb + 32768u + sw);
            }
#pragma unroll
            for (int p2 = 0; p2 < 8; p2++) {
                int nrow = p2 * 16 + ((sub >> 1) << 3) + rr;
                uint32_t off = (uint32_t)(nrow * 256 + ks * 32 + ((sub & 1) << 4));
                uint32_t sw = off ^ (((off >> 8) & 7) << 4);
                LDSM_X4(bh[p2 * 4], bh[p2 * 4 + 1], bh[p2 * 4 + 2], bh[p2 * 4 + 3], bbase + sw);
                LDSM_X4(bl[p2 * 4], bl[p2 * 4 + 1], bl[p2 * 4 + 2], bl[p2 * 4 + 3], bbase + 32768u + sw);
            }
#pragma unroll
            for (int nf = 0; nf < 16; nf++) {
                mma16816(acc[nf], ah, &bh[nf * 2]);
                mma16816(acc[nf], ah, &bl[nf * 2]);
                mma16816(acc[nf], al, &bh[nf * 2]);
            }
        }

        // --- warp-local online softmax (rows: wrow+lg, wrow+lg+8) ---
        float mnew[2], rfac[2], tsum[2];
#pragma unroll
        for (int h = 0; h < 2; h++) {
            float v = -1e30f;
#pragma unroll
            for (int nf = 0; nf < 16; nf++)
                v = fmaxf(v, fmaxf(acc[nf][2 * h], acc[nf][2 * h + 1]));
            v = fmaxf(v, __shfl_xor_sync(0xffffffffu, v, 1));
            v = fmaxf(v, __shfl_xor_sync(0xffffffffu, v, 2));
            float mn = fmaxf(m_run[h], v);
            mnew[h] = mn;
            rfac[h] = __expf(m_run[h] - mn);
            s_run[h] *= rfac[h];
            tsum[h] = 0.0f;
        }
#pragma unroll
        for (int nf = 0; nf < 16; nf++) {
            acc[nf][0] = __expf(acc[nf][0] - mnew[0]);
            acc[nf][1] = __expf(acc[nf][1] - mnew[0]);
            acc[nf][2] = __expf(acc[nf][2] - mnew[1]);
            acc[nf][3] = __expf(acc[nf][3] - mnew[1]);
            tsum[0] += acc[nf][0] + acc[nf][1];
            tsum[1] += acc[nf][2] + acc[nf][3];
        }
#pragma unroll
        for (int h = 0; h < 2; h++) {
            float v = tsum[h];
            v += __shfl_xor_sync(0xffffffffu, v, 1);
            v += __shfl_xor_sync(0xffffffffu, v, 2);
            s_run[h] += v;
            m_run[h] = mnew[h];
        }

        // --- store p tile (fp16) and rescale factors ---
        {
            const int row0 = m0 + wrow + lg;
            __half* P0 = P + (size_t)row0 * N_ADDR + t * 128 + lt * 2;
            __half* P1 = P0 + 8 * N_ADDR;
#pragma unroll
            for (int nf = 0; nf < 16; nf++) {
                *(__half2*)(P0 + nf * 8) = __floats2half2_rn(acc[nf][0], acc[nf][1]);
                *(__half2*)(P1 + nf * 8) = __floats2half2_rn(acc[nf][2], acc[nf][3]);
            }
        }
        if (lt == 0) {
            R[(size_t)t * M_TOT + m0 + wrow + lg]     = rfac[0];
            R[(size_t)t * M_TOT + m0 + wrow + lg + 8] = rfac[1];
        }
    }

    if (lt == 0) {
        SINV[m0 + wrow + lg]     = 1.0f / s_run[0];
        SINV[m0 + wrow + lg + 8] = 1.0f / s_run[1];
    }
}

// ---------------------------------------------------------------------------
// Pass 2: out[M,V] = (P @ PBT^T) with prefetched flash rescale per k-tile.
// CTA tile 128x128, 8 warps, KC=64, cp.async 3-stage pipeline.
// ---------------------------------------------------------------------------
__global__ __launch_bounds__(256, 2) void out_gemm(
    const __half* __restrict__ P, const __half* __restrict__ PBT,
    float* __restrict__ C,
    const float* __restrict__ R, const float* __restrict__ SINV)
{
    extern __shared__ char sm[];
    const uint32_t sb = smem_u32(sm);
    const int tid = threadIdx.x, lane = tid & 31, wid = tid >> 5;
    const int wm = wid & 1, wn = wid >> 1;
    const int m0 = blockIdx.y * 128, n0 = blockIdx.x * 128;
    constexpr int CHUNKS = N_ADDR / 64;
    const int sub = lane >> 3, rr = lane & 7;
    const int lg = lane >> 2, lt = lane & 3;

    int rowg[4][2];
#pragma unroll
    for (int mf = 0; mf < 4; mf++)
#pragma unroll
        for (int h = 0; h < 2; h++)
            rowg[mf][h] = m0 + wm * 64 + mf * 16 + lg + 8 * h;

    auto issue = [&](int st, int ci) {
        const uint32_t base = (uint32_t)st * 32768u;
        const int k0 = ci * 64;
#pragma unroll
        for (int s = 0; s < 4; s++) {
            int idx = tid + s * 256;
            int r = idx >> 3, b = idx & 7;
            uint32_t off = (uint32_t)(r * 128 + b * 16);
            uint32_t sw = off ^ ((off >> 3) & 0x70);
            cp16(sb + base + sw,          P   + (size_t)(m0 + r) * N_ADDR + k0 + b * 8);
            cp16(sb + base + 16384 + sw,  PBT + (size_t)(n0 + r) * N_ADDR + k0 + b * 8);
        }
        CP_COMMIT();
    };

    float acc[4][4][4];
#pragma unroll
    for (int i = 0; i < 4; i++)
#pragma unroll
        for (int j = 0; j < 4; j++)
#pragma unroll
            for (int k = 0; k < 4; k++) acc[i][j][k] = 0.0f;

    issue(0, 0);
    issue(1, 1);

    // Prefetch rescale factors for tile 0.
    float rvn[4][2];
#pragma unroll
    for (int mf = 0; mf < 4; mf++)
#pragma unroll
        for (int h = 0; h < 2; h++)
            rvn[mf][h] = __ldg(R + rowg[mf][h]);        // t = 0

    for (int ci = 0; ci < CHUNKS; ci++) {
        const int st = ci % 3;
        CP_WAIT1();
        __syncthreads();
        if (ci + 2 < CHUNKS) issue((ci + 2) % 3, ci + 2);

        if ((ci & 1) == 0) {
            const int t = ci >> 1;
            float rv[4][2];
#pragma unroll
            for (int mf = 0; mf < 4; mf++)
#pragma unroll
                for (int h = 0; h < 2; h++) rv[mf][h] = rvn[mf][h];
            if (t + 1 < NTILES) {
#pragma unroll
                for (int mf = 0; mf < 4; mf++)
#pragma unroll
                    for (int h = 0; h < 2; h++)
                        rvn[mf][h] = __ldg(R + (size_t)(t + 1) * M_TOT + rowg[mf][h]);
            }
#pragma unroll
            for (int mf = 0; mf < 4; mf++)
#pragma unroll
                for (int nf = 0; nf < 4; nf++) {
                    acc[mf][nf][0] *= rv[mf][0];
                    acc[mf][nf][1] *= rv[mf][0];
                    acc[mf][nf][2] *= rv[mf][1];
                    acc[mf][nf][3] *= rv[mf][1];
                }
        }

        const uint32_t ab = sb + (uint32_t)st * 32768u;
        const uint32_t bb = ab + 16384u;
#pragma unroll
        for (int ks = 0; ks < 4; ks++) {
            uint32_t a[4][4];
#pragma unroll
            for (int mf = 0; mf < 4; mf++) {
                int row = wm * 64 + mf * 16 + ((sub & 1) << 3) + rr;
                uint32_t off = (uint32_t)(row * 128 + ks * 32 + ((sub >> 1) << 4));
                uint32_t sw = off ^ ((off >> 3) & 0x70);
                LDSM_X4(a[mf][0], a[mf][1], a[mf][2], a[mf][3], ab + sw);
            }
            uint32_t bf[8];
#pragma unroll
            for (int p2 = 0; p2 < 2; p2++) {
                int nrow = wn * 32 + (p2 * 2 + (sub >> 1)) * 8 + rr;
                uint32_t off = (uint32_t)(nrow * 128 + ks * 32 + ((sub & 1) << 4));
                uint32_t sw = off ^ ((off >> 3) & 0x70);
                LDSM_X4(bf[p2 * 4], bf[p2 * 4 + 1], bf[p2 * 4 + 2], bf[p2 * 4 + 3], bb + sw);
            }
#pragma unroll
            for (int mf = 0; mf < 4; mf++)
#pragma unroll
                for (int nf = 0; nf < 4; nf++)
                    mma16816(acc[mf][nf], a[mf], &bf[nf * 2]);
        }
    }

#pragma unroll
    for (int mf = 0; mf < 4; mf++) {
        const float s0 = __ldg(SINV + rowg[mf][0]);
        const float s1 = __ldg(SINV + rowg[mf][1]);
#pragma unroll
        for (int nf = 0; nf < 4; nf++) {
            const int col = n0 + wn * 32 + nf * 8 + lt * 2;
            *(float2*)(C + (size_t)rowg[mf][0] * V_DIM + col) =
                make_float2(acc[mf][nf][0] * s0, acc[mf][nf][1] * s0);
            *(float2*)(C + (size_t)rowg[mf][1] * V_DIM + col) =
                make_float2(acc[mf][nf][2] * s1, acc[mf][nf][3] * s1);
        }
    }
}

// ---------------------------------------------------------------------------
// Prep: AS f32 -> hi/lo fp16 arrays.
// ---------------------------------------------------------------------------
__global__ __launch_bounds__(256) void convert_as(
    const float* __restrict__ AS, __half* __restrict__ Hh, __half* __restrict__ Hl)
{
    const int i = blockIdx.x * 256 + threadIdx.x;   // each handles 8 floats
    const float4 v0 = ((const float4*)AS)[i * 2];
    const float4 v1 = ((const float4*)AS)[i * 2 + 1];
    float f[8] = {v0.x, v0.y, v0.z, v0.w, v1.x, v1.y, v1.z, v1.w};
    uint32_t hh[4], ll[4];
#pragma unroll
    for (int j = 0; j < 4; j++) {
        __half h0 = __float2half_rn(f[2 * j]);
        __half h1 = __float2half_rn(f[2 * j + 1]);
        __half l0 = __float2half_rn(f[2 * j]     - __half2float(h0));
        __half l1 = __float2half_rn(f[2 * j + 1] - __half2float(h1));
        __half2 hp = __halves2half2(h0, h1);
        __half2 lp = __halves2half2(l0, l1);
        hh[j] = *(uint32_t*)&hp; ll[j] = *(uint32_t*)&lp;
    }
    ((uint4*)Hh)[i] = make_uint4(hh[0], hh[1], hh[2], hh[3]);
    ((uint4*)Hl)[i] = make_uint4(ll[0], ll[1], ll[2], ll[3]);
}

// ---------------------------------------------------------------------------
// param_bank [N,V] f32 -> PBT [V,N] fp16
// ---------------------------------------------------------------------------
__global__ __launch_bounds__(256) void transpose_pb(
    const float* __restrict__ PB, __half* __restrict__ PBT)
{
    __shared__ float t[32][33];
    const int bx = blockIdx.x * 32;  // V
    const int by = blockIdx.y * 32;  // N
    const int x = threadIdx.x & 31;
    const int y = threadIdx.x >> 5;
#pragma unroll
    for (int j = 0; j < 32; j += 8)
        t[y + j][x] = PB[(size_t)(by + y + j) * V_DIM + bx + x];
    __syncthreads();
#pragma unroll
    for (int j = 0; j < 32; j += 8)
        PBT[(size_t)(bx + y + j) * N_ADDR + by + x] = __float2half_rn(t[x][y + j]);
}

// ---------------------------------------------------------------------------
extern "C" void kernel_launch(void* const* d_in, const int* in_sizes, int n_in,
                              void* d_out, int out_size)
{
    const float* selector      = (const float*)d_in[0];  // [16384, 128]
    const float* param_bank    = (const float*)d_in[1];  // [4096, 512]
    const float* address_space = (const float*)d_in[2];  // [4096, 128]
    float* out = (float*)d_out;                          // [16384, 512]

    __half* p;    cudaGetSymbolAddress((void**)&p,    g_p);
    __half* pbt;  cudaGetSymbolAddress((void**)&pbt,  g_pbt);
    __half* ash;  cudaGetSymbolAddress((void**)&ash,  g_ash);
    __half* asl;  cudaGetSymbolAddress((void**)&asl,  g_asl);
    float*  rbuf; cudaGetSymbolAddress((void**)&rbuf, g_r);
    float*  sinv; cudaGetSymbolAddress((void**)&sinv, g_sinv);

    constexpr uint32_t SMEM1 = 196608;  // Sh+Sl (64K) + 2 B-stages (128K)
    constexpr uint32_t SMEM2 = 98304;   // 3 x 32KB stages
    cudaFuncSetAttribute(score_pass, cudaFuncAttributeMaxDynamicSharedMemorySize, SMEM1);
    cudaFuncSetAttribute(out_gemm,   cudaFuncAttributeMaxDynamicSharedMemorySize, SMEM2);

    transpose_pb<<<dim3(V_DIM / 32, N_ADDR / 32), 256>>>(param_bank, pbt);
    convert_as<<<(N_ADDR * D_DIM / 8) / 256, 256>>>(address_space, ash, asl);

    score_pass<<<M_TOT / 128, 256, SMEM1>>>(selector, ash, asl, p, rbuf, sinv);

    out_gemm<<<dim3(V_DIM / 128, M_TOT / 128), 256, SMEM2>>>(p, pbt, out, rbuf, sinv);
}

// round 8
// speedup vs baseline: 6.7355x; 1.0279x over previous
#include <cuda_runtime.h>
#include <cuda_fp16.h>
#include <cstdint>

// SoftAddressSpace: out[M,V] = softmax(selector[M,D] @ AS[N,D]^T) @ PB[N,V]
// M=16384, D=128, N=4096, V=512, fp32 in/out.
// R7: flash 2-pass.
//   pass1: warp-owns-rows online softmax (unchanged from R6).
//   pass2: rescale HOISTED above the pipeline wait (overlaps cp.async) and
//          skipped via warp-vote when all factors are exactly 1.0.
//   prep:  transpose_pb + convert_as merged into one launch.

#define M_TOT  16384
#define N_ADDR 4096
#define D_DIM  128
#define V_DIM  512
#define NTILES (N_ADDR / 128)   // 32

static __device__ __half g_p   [(size_t)M_TOT * N_ADDR];   // fp16 p (128 MiB)
static __device__ __half g_pbt [(size_t)V_DIM * N_ADDR];   // fp16 PB^T (4 MiB)
static __device__ __half g_ash [(size_t)N_ADDR * D_DIM];   // AS hi (1 MiB)
static __device__ __half g_asl [(size_t)N_ADDR * D_DIM];   // AS lo (1 MiB)
static __device__ float  g_r   [(size_t)NTILES * M_TOT];   // rescale, [t][row]
static __device__ float  g_sinv[(size_t)M_TOT];            // 1/sum per row

__device__ __forceinline__ uint32_t smem_u32(const void* p) {
    uint32_t a;
    asm("{ .reg .u64 t; cvta.to.shared.u64 t, %1; cvt.u32.u64 %0, t; }" : "=r"(a) : "l"(p));
    return a;
}

#define LDSM_X4(r0, r1, r2, r3, addr) \
    asm volatile("ldmatrix.sync.aligned.m8n8.x4.shared.b16 {%0,%1,%2,%3}, [%4];" \
                 : "=r"(r0), "=r"(r1), "=r"(r2), "=r"(r3) : "r"(addr))

__device__ __forceinline__ void mma16816(float* d, const uint32_t* a, const uint32_t* b) {
    asm volatile(
        "mma.sync.aligned.m16n8k16.row.col.f32.f16.f16.f32 "
        "{%0,%1,%2,%3}, {%4,%5,%6,%7}, {%8,%9}, {%0,%1,%2,%3};"
        : "+f"(d[0]), "+f"(d[1]), "+f"(d[2]), "+f"(d[3])
        : "r"(a[0]), "r"(a[1]), "r"(a[2]), "r"(a[3]), "r"(b[0]), "r"(b[1]));
}

__device__ __forceinline__ void cp16(uint32_t dst, const void* src) {
    asm volatile("cp.async.cg.shared.global [%0], [%1], 16;" :: "r"(dst), "l"(src));
}
#define CP_COMMIT() asm volatile("cp.async.commit_group;" ::: "memory")
#define CP_WAIT1()  asm volatile("cp.async.wait_group 1;" ::: "memory")
#define CP_WAIT0()  asm volatile("cp.async.wait_group 0;" ::: "memory")

// ---------------------------------------------------------------------------
// Pass 1: grid = 128 CTAs, each owns a 128-row strip; warp w owns rows
// [w*16, w*16+16). Smem: Sh @0 (32K), Sl @32K, B stages @64K (2 x [Bh|Bl] 64K).
// 256B smem rows; swizzle off ^ (((off>>8)&7)<<4). One syncthreads per tile.
// ---------------------------------------------------------------------------
__global__ __launch_bounds__(256, 1) void score_pass(
    const float* __restrict__ S,
    const __half* __restrict__ ASh, const __half* __restrict__ ASl,
    __half* __restrict__ P, float* __restrict__ R, float* __restrict__ SINV)
{
    extern __shared__ char sm[];
    const uint32_t sb = smem_u32(sm);
    const int tid = threadIdx.x, lane = tid & 31, wid = tid >> 5;
    const int m0 = blockIdx.x * 128;
    const int sub = lane >> 3, rr = lane & 7;
    const int lg = lane >> 2, lt = lane & 3;
    const int wrow = wid * 16;

    // --- load + hi/lo convert selector strip (resident) ---
#pragma unroll
    for (int s = 0; s < 8; s++) {
        int idx = tid + s * 256;
        int r = idx >> 4, b = idx & 15;
        uint32_t off = (uint32_t)(r * 256 + b * 16);
        uint32_t sw = off ^ (((off >> 8) & 7) << 4);
        const float* src = S + (size_t)(m0 + r) * D_DIM + b * 8;
        float4 v0 = *(const float4*)src, v1 = *(const float4*)(src + 4);
        float f[8] = {v0.x, v0.y, v0.z, v0.w, v1.x, v1.y, v1.z, v1.w};
        uint32_t hh[4], ll[4];
#pragma unroll
        for (int j = 0; j < 4; j++) {
            __half h0 = __float2half_rn(f[2 * j]);
            __half h1 = __float2half_rn(f[2 * j + 1]);
            __half l0 = __float2half_rn(f[2 * j]     - __half2float(h0));
            __half l1 = __float2half_rn(f[2 * j + 1] - __half2float(h1));
            __half2 hp = __halves2half2(h0, h1);
            __half2 lp = __halves2half2(l0, l1);
            hh[j] = *(uint32_t*)&hp; ll[j] = *(uint32_t*)&lp;
        }
        *(uint4*)(sm + sw)          = make_uint4(hh[0], hh[1], hh[2], hh[3]);
        *(uint4*)(sm + 32768u + sw) = make_uint4(ll[0], ll[1], ll[2], ll[3]);
    }

    auto issueB = [&](int st, int t) {
        const uint32_t base = 65536u + (uint32_t)st * 65536u;
#pragma unroll
        for (int s = 0; s < 8; s++) {
            int idx = tid + s * 256;
            int r = idx >> 4, b = idx & 15;
            uint32_t off = (uint32_t)(r * 256 + b * 16);
            uint32_t sw = off ^ (((off >> 8) & 7) << 4);
            const size_t go = (size_t)(t * 128 + r) * D_DIM + b * 8;
            cp16(sb + base + sw,          ASh + go);
            cp16(sb + base + 32768u + sw, ASl + go);
        }
        CP_COMMIT();
    };

    issueB(0, 0);

    float m_run[2] = {-1e30f, -1e30f}, s_run[2] = {0.0f, 0.0f};

    for (int t = 0; t < NTILES; t++) {
        CP_WAIT0();
        __syncthreads();
        if (t + 1 < NTILES) issueB((t + 1) & 1, t + 1);

        const uint32_t bbase = sb + 65536u + (uint32_t)(t & 1) * 65536u;

        float acc[16][4];
#pragma unroll
        for (int i = 0; i < 16; i++)
#pragma unroll
            for (int k = 0; k < 4; k++) acc[i][k] = 0.0f;

#pragma unroll
        for (int ks = 0; ks < 8; ks++) {
            uint32_t ah[4], al[4], bh[32], bl[32];
            {
                int row = wrow + ((sub & 1) << 3) + rr;
                uint32_t off = (uint32_t)(row * 256 + ks * 32 + ((sub >> 1) << 4));
                uint32_t sw = off ^ (((off >> 8) & 7) << 4);
                LDSM_X4(ah[0], ah[1], ah[2], ah[3], sb + sw);
                LDSM_X4(al[0], al[1], al[2], al[3], sb + 32768u + sw);
            }
#pragma unroll
            for (int p2 = 0; p2 < 8; p2++) {
                int nrow = p2 * 16 + ((sub >> 1) << 3) + rr;
                uint32_t off = (uint32_t)(nrow * 256 + ks * 32 + ((sub & 1) << 4));
                uint32_t sw = off ^ (((off >> 8) & 7) << 4);
                LDSM_X4(bh[p2 * 4], bh[p2 * 4 + 1], bh[p2 * 4 + 2], bh[p2 * 4 + 3], bbase + sw);
                LDSM_X4(bl[p2 * 4], bl[p2 * 4 + 1], bl[p2 * 4 + 2], bl[p2 * 4 + 3], bbase + 32768u + sw);
            }
#pragma unroll
            for (int nf = 0; nf < 16; nf++) {
                mma16816(acc[nf], ah, &bh[nf * 2]);
                mma16816(acc[nf], ah, &bl[nf * 2]);
                mma16816(acc[nf], al, &bh[nf * 2]);
            }
        }

        // --- warp-local online softmax (rows: wrow+lg, wrow+lg+8) ---
        float mnew[2], rfac[2], tsum[2];
#pragma unroll
        for (int h = 0; h < 2; h++) {
            float v = -1e30f;
#pragma unroll
            for (int nf = 0; nf < 16; nf++)
                v = fmaxf(v, fmaxf(acc[nf][2 * h], acc[nf][2 * h + 1]));
            v = fmaxf(v, __shfl_xor_sync(0xffffffffu, v, 1));
            v = fmaxf(v, __shfl_xor_sync(0xffffffffu, v, 2));
            float mn = fmaxf(m_run[h], v);
            mnew[h] = mn;
            rfac[h] = __expf(m_run[h] - mn);
            s_run[h] *= rfac[h];
            tsum[h] = 0.0f;
        }
#pragma unroll
        for (int nf = 0; nf < 16; nf++) {
            acc[nf][0] = __expf(acc[nf][0] - mnew[0]);
            acc[nf][1] = __expf(acc[nf][1] - mnew[0]);
            acc[nf][2] = __expf(acc[nf][2] - mnew[1]);
            acc[nf][3] = __expf(acc[nf][3] - mnew[1]);
            tsum[0] += acc[nf][0] + acc[nf][1];
            tsum[1] += acc[nf][2] + acc[nf][3];
        }
#pragma unroll
        for (int h = 0; h < 2; h++) {
            float v = tsum[h];
            v += __shfl_xor_sync(0xffffffffu, v, 1);
            v += __shfl_xor_sync(0xffffffffu, v, 2);
            s_run[h] += v;
            m_run[h] = mnew[h];
        }

        // --- store p tile (fp16) and rescale factors ---
        {
            const int row0 = m0 + wrow + lg;
            __half* P0 = P + (size_t)row0 * N_ADDR + t * 128 + lt * 2;
            __half* P1 = P0 + 8 * N_ADDR;
#pragma unroll
            for (int nf = 0; nf < 16; nf++) {
                *(__half2*)(P0 + nf * 8) = __floats2half2_rn(acc[nf][0], acc[nf][1]);
                *(__half2*)(P1 + nf * 8) = __floats2half2_rn(acc[nf][2], acc[nf][3]);
            }
        }
        if (lt == 0) {
            R[(size_t)t * M_TOT + m0 + wrow + lg]     = rfac[0];
            R[(size_t)t * M_TOT + m0 + wrow + lg + 8] = rfac[1];
        }
    }

    if (lt == 0) {
        SINV[m0 + wrow + lg]     = 1.0f / s_run[0];
        SINV[m0 + wrow + lg + 8] = 1.0f / s_run[1];
    }
}

// ---------------------------------------------------------------------------
// Pass 2: out[M,V] = (P @ PBT^T), flash rescale hoisted above pipeline wait
// and vote-skipped when all factors are exactly 1.0.
// ---------------------------------------------------------------------------
__global__ __launch_bounds__(256, 2) void out_gemm(
    const __half* __restrict__ P, const __half* __restrict__ PBT,
    float* __restrict__ C,
    const float* __restrict__ R, const float* __restrict__ SINV)
{
    extern __shared__ char sm[];
    const uint32_t sb = smem_u32(sm);
    const int tid = threadIdx.x, lane = tid & 31, wid = tid >> 5;
    const int wm = wid & 1, wn = wid >> 1;
    const int m0 = blockIdx.y * 128, n0 = blockIdx.x * 128;
    constexpr int CHUNKS = N_ADDR / 64;
    const int sub = lane >> 3, rr = lane & 7;
    const int lg = lane >> 2, lt = lane & 3;

    int rowg[4][2];
#pragma unroll
    for (int mf = 0; mf < 4; mf++)
#pragma unroll
        for (int h = 0; h < 2; h++)
            rowg[mf][h] = m0 + wm * 64 + mf * 16 + lg + 8 * h;

    auto issue = [&](int st, int ci) {
        const uint32_t base = (uint32_t)st * 32768u;
        const int k0 = ci * 64;
#pragma unroll
        for (int s = 0; s < 4; s++) {
            int idx = tid + s * 256;
            int r = idx >> 3, b = idx & 7;
            uint32_t off = (uint32_t)(r * 128 + b * 16);
            uint32_t sw = off ^ ((off >> 3) & 0x70);
            cp16(sb + base + sw,          P   + (size_t)(m0 + r) * N_ADDR + k0 + b * 8);
            cp16(sb + base + 16384 + sw,  PBT + (size_t)(n0 + r) * N_ADDR + k0 + b * 8);
        }
        CP_COMMIT();
    };

    float acc[4][4][4];
#pragma unroll
    for (int i = 0; i < 4; i++)
#pragma unroll
        for (int j = 0; j < 4; j++)
#pragma unroll
            for (int k = 0; k < 4; k++) acc[i][j][k] = 0.0f;

    issue(0, 0);
    issue(1, 1);

    // Prefetch rescale factors for tile 0.
    float rvn[4][2];
#pragma unroll
    for (int mf = 0; mf < 4; mf++)
#pragma unroll
        for (int h = 0; h < 2; h++)
            rvn[mf][h] = __ldg(R + rowg[mf][h]);

    for (int ci = 0; ci < CHUNKS; ci++) {
        const int st = ci % 3;

        // --- flash rescale BEFORE the pipeline wait: overlaps cp.async; ---
        // --- skipped entirely (warp-uniform) when all factors are 1.0.  ---
        if ((ci & 1) == 0) {
            const int t = ci >> 1;
            bool one = true;
#pragma unroll
            for (int mf = 0; mf < 4; mf++)
#pragma unroll
                for (int h = 0; h < 2; h++) one &= (rvn[mf][h] == 1.0f);
            if (!__all_sync(0xffffffffu, one)) {
#pragma unroll
                for (int mf = 0; mf < 4; mf++)
#pragma unroll
                    for (int nf = 0; nf < 4; nf++) {
                        acc[mf][nf][0] *= rvn[mf][0];
                        acc[mf][nf][1] *= rvn[mf][0];
                        acc[mf][nf][2] *= rvn[mf][1];
                        acc[mf][nf][3] *= rvn[mf][1];
                    }
            }
            if (t + 1 < NTILES) {
#pragma unroll
                for (int mf = 0; mf < 4; mf++)
#pragma unroll
                    for (int h = 0; h < 2; h++)
                        rvn[mf][h] = __ldg(R + (size_t)(t + 1) * M_TOT + rowg[mf][h]);
            }
        }

        CP_WAIT1();
        __syncthreads();
        if (ci + 2 < CHUNKS) issue((ci + 2) % 3, ci + 2);

        const uint32_t ab = sb + (uint32_t)st * 32768u;
        const uint32_t bb = ab + 16384u;
#pragma unroll
        for (int ks = 0; ks < 4; ks++) {
            uint32_t a[4][4];
#pragma unroll
            for (int mf = 0; mf < 4; mf++) {
                int row = wm * 64 + mf * 16 + ((sub & 1) << 3) + rr;
                uint32_t off = (uint32_t)(row * 128 + ks * 32 + ((sub >> 1) << 4));
                uint32_t sw = off ^ ((off >> 3) & 0x70);
                LDSM_X4(a[mf][0], a[mf][1], a[mf][2], a[mf][3], ab + sw);
            }
            uint32_t bf[8];
#pragma unroll
            for (int p2 = 0; p2 < 2; p2++) {
                int nrow = wn * 32 + (p2 * 2 + (sub >> 1)) * 8 + rr;
                uint32_t off = (uint32_t)(nrow * 128 + ks * 32 + ((sub & 1) << 4));
                uint32_t sw = off ^ ((off >> 3) & 0x70);
                LDSM_X4(bf[p2 * 4], bf[p2 * 4 + 1], bf[p2 * 4 + 2], bf[p2 * 4 + 3], bb + sw);
            }
#pragma unroll
            for (int mf = 0; mf < 4; mf++)
#pragma unroll
                for (int nf = 0; nf < 4; nf++)
                    mma16816(acc[mf][nf], a[mf], &bf[nf * 2]);
        }
    }

#pragma unroll
    for (int mf = 0; mf < 4; mf++) {
        const float s0 = __ldg(SINV + rowg[mf][0]);
        const float s1 = __ldg(SINV + rowg[mf][1]);
#pragma unroll
        for (int nf = 0; nf < 4; nf++) {
            const int col = n0 + wn * 32 + nf * 8 + lt * 2;
            *(float2*)(C + (size_t)rowg[mf][0] * V_DIM + col) =
                make_float2(acc[mf][nf][0] * s0, acc[mf][nf][1] * s0);
            *(float2*)(C + (size_t)rowg[mf][1] * V_DIM + col) =
                make_float2(acc[mf][nf][2] * s1, acc[mf][nf][3] * s1);
        }
    }
}

// ---------------------------------------------------------------------------
// Merged prep: blocks [0, 2048) transpose PB -> fp16 PBT; [2048, 2304) convert
// AS -> hi/lo fp16.
// ---------------------------------------------------------------------------
__global__ __launch_bounds__(256) void prep_kernel(
    const float* __restrict__ PB, __half* __restrict__ PBT,
    const float* __restrict__ AS, __half* __restrict__ Hh, __half* __restrict__ Hl)
{
    if (blockIdx.x < 2048) {
        __shared__ float t[32][33];
        const int bx = (blockIdx.x & 15) * 32;   // V
        const int by = (blockIdx.x >> 4) * 32;   // N
        const int x = threadIdx.x & 31;
        const int y = threadIdx.x >> 5;
#pragma unroll
        for (int j = 0; j < 32; j += 8)
            t[y + j][x] = PB[(size_t)(by + y + j) * V_DIM + bx + x];
        __syncthreads();
#pragma unroll
        for (int j = 0; j < 32; j += 8)
            PBT[(size_t)(bx + y + j) * N_ADDR + by + x] = __float2half_rn(t[x][y + j]);
    } else {
        const int i = (blockIdx.x - 2048) * 256 + threadIdx.x;  // 8 floats each
        const float4 v0 = ((const float4*)AS)[i * 2];
        const float4 v1 = ((const float4*)AS)[i * 2 + 1];
        float f[8] = {v0.x, v0.y, v0.z, v0.w, v1.x, v1.y, v1.z, v1.w};
        uint32_t hh[4], ll[4];
#pragma unroll
        for (int j = 0; j < 4; j++) {
            __half h0 = __float2half_rn(f[2 * j]);
            __half h1 = __float2half_rn(f[2 * j + 1]);
            __half l0 = __float2half_rn(f[2 * j]     - __half2float(h0));
            __half l1 = __float2half_rn(f[2 * j + 1] - __half2float(h1));
            __half2 hp = __halves2half2(h0, h1);
            __half2 lp = __halves2half2(l0, l1);
            hh[j] = *(uint32_t*)&hp; ll[j] = *(uint32_t*)&lp;
        }
        ((uint4*)Hh)[i] = make_uint4(hh[0], hh[1], hh[2], hh[3]);
        ((uint4*)Hl)[i] = make_uint4(ll[0], ll[1], ll[2], ll[3]);
    }
}

// ---------------------------------------------------------------------------
extern "C" void kernel_launch(void* const* d_in, const int* in_sizes, int n_in,
                              void* d_out, int out_size)
{
    const float* selector      = (const float*)d_in[0];  // [16384, 128]
    const float* param_bank    = (const float*)d_in[1];  // [4096, 512]
    const float* address_space = (const float*)d_in[2];  // [4096, 128]
    float* out = (float*)d_out;                          // [16384, 512]

    __half* p;    cudaGetSymbolAddress((void**)&p,    g_p);
    __half* pbt;  cudaGetSymbolAddress((void**)&pbt,  g_pbt);
    __half* ash;  cudaGetSymbolAddress((void**)&ash,  g_ash);
    __half* asl;  cudaGetSymbolAddress((void**)&asl,  g_asl);
    float*  rbuf; cudaGetSymbolAddress((void**)&rbuf, g_r);
    float*  sinv; cudaGetSymbolAddress((void**)&sinv, g_sinv);

    constexpr uint32_t SMEM1 = 196608;  // Sh+Sl (64K) + 2 B-stages (128K)
    constexpr uint32_t SMEM2 = 98304;   // 3 x 32KB stages
    cudaFuncSetAttribute(score_pass, cudaFuncAttributeMaxDynamicSharedMemorySize, SMEM1);
    cudaFuncSetAttribute(out_gemm,   cudaFuncAttributeMaxDynamicSharedMemorySize, SMEM2);

    prep_kernel<<<2048 + (N_ADDR * D_DIM / 8) / 256, 256>>>(
        param_bank, pbt, address_space, ash, asl);

    score_pass<<<M_TOT / 128, 256, SMEM1>>>(selector, ash, asl, p, rbuf, sinv);

    out_gemm<<<dim3(V_DIM / 128, M_TOT / 128), 256, SMEM2>>>(p, pbt, out, rbuf, sinv);
}